// round 8
// baseline (speedup 1.0000x reference)
#include <cuda_runtime.h>
#include <cuda_bf16.h>
#include <cstdint>

#define T_TOK 2048
#define H_DIM 2048
#define F_DIM 1024
#define NEXP  16
#define TOPK  4
#define NSLOT (T_TOK * TOPK)   // 8192

// ---------------- device scratch ----------------
__device__ float   g_act[(size_t)NSLOT * F_DIM];                    // 32 MB
__device__ uint8_t g_guw[(size_t)NEXP * 2 * F_DIM * (H_DIM / 2)];   // 33.5 MB packed
__device__ uint8_t g_dwn[(size_t)NEXP * H_DIM * (F_DIM / 2)];       // 16.8 MB packed

// resolved pointers: 0=x 1=ids 2=wts 3=guw 4=gus 5=dwn 6=dsc
__device__ const void* g_rp[7];
// dtype flags: float-ish slots {0,2,4,6}: 0=f32 1=bf16. ids slot 1: 0=i32 2=i64 3=f32.
// weight slots {3,5}: 0=packed u8, 3=int32 bytes, 4=f32 bytes, 5=int64 bytes. [7]=out bf16.
__device__ int g_bf[8];

struct InPtrs { const void* p[8]; long long sz[8]; int n; };

__device__ __forceinline__ float bfh(unsigned h) { return __uint_as_float(h << 16); }

// ---------------- content+dtype based input resolution ----------------
__global__ void k_resolve(InPtrs in) {
    __shared__ int cls[8], bff[8];
    __shared__ long long ssz[8];
    int w = threadIdx.x >> 5, lane = threadIdx.x & 31;
    if (w < 8 && lane == 0) { cls[w] = -1; bff[w] = 0; ssz[w] = 0; }
    __syncthreads();
    if (w < in.n && w < 8) {
        const unsigned* u = (const unsigned*)in.p[w];
        bool lt16 = true, i64ids = true, i64b = true, u32b = true;
        bool fint16 = true, fint256 = true;
        bool f32unit = true, f32mant0 = true, f32small = true;
        bool bfunit = true, bfpow2 = true, bfsmall = true;
        bool neg32 = false, pos32 = false, negB = false, posB = false;
        #pragma unroll
        for (int j = 0; j < 4; j++) {
            int idx = lane + 32 * j;
            unsigned v = u[idx];
            lt16   &= (v < 16u);
            i64ids &= (idx & 1) ? (v == 0u) : (v < 16u);
            i64b   &= (idx & 1) ? (v == 0u) : (v < 256u);
            u32b   &= (v < 256u);
            float f = __uint_as_float(v);
            unsigned ex = (v >> 23) & 255u;
            bool fin = (ex != 255u);
            bool isint = fin && f >= 0.f && f == floorf(f);
            fint16  &= (isint && f < 16.f);
            fint256 &= (isint && f < 256.f);
            f32unit  &= (fin && f > 0.f && f < 1.f);
            f32mant0 &= ((v & 0x7FFFFFu) == 0u);
            f32small &= (fin && fabsf(f) < 100.f);
            neg32 |= (f < 0.f); pos32 |= (f > 0.f);
            unsigned hs[2] = { v >> 16, v & 0xFFFFu };
            #pragma unroll
            for (int q = 0; q < 2; q++) {
                unsigned h = hs[q];
                float fb = bfh(h);
                bool finB = (((h >> 7) & 255u) != 255u);
                bfunit  &= (finB && fb > 0.f && fb < 1.f);
                bfpow2  &= (finB && fb > 0.f && fb < 1.f && ((h & 127u) == 0u));
                bfsmall &= (finB && fabsf(fb) < 100.f);
                negB |= (fb < 0.f); posB |= (fb > 0.f);
            }
        }
        unsigned full = ~0u;
        lt16 = __all_sync(full, lt16);       i64ids = __all_sync(full, i64ids);
        i64b = __all_sync(full, i64b);       u32b = __all_sync(full, u32b);
        fint16 = __all_sync(full, fint16);   fint256 = __all_sync(full, fint256);
        f32unit = __all_sync(full, f32unit); f32mant0 = __all_sync(full, f32mant0);
        f32small = __all_sync(full, f32small);
        bfunit = __all_sync(full, bfunit);   bfpow2 = __all_sync(full, bfpow2);
        bfsmall = __all_sync(full, bfsmall);
        neg32 = __any_sync(full, neg32);     pos32 = __any_sync(full, pos32);
        negB = __any_sync(full, negB);       posB = __any_sync(full, posB);
        if (lane == 0) {
            int c, bf = 0;
            if (lt16)                         { c = 0; }           // int32 ids
            else if (i64ids)                  { c = 0; bf = 2; }   // int64 ids
            else if (fint16)                  { c = 0; bf = 3; }   // f32 ids
            else if (i64b)                    { c = 4; bf = 5; }   // int64-expanded bytes
            else if (u32b)                    { c = 4; bf = 3; }   // int32-expanded bytes
            else if (fint256)                 { c = 4; bf = 4; }   // f32-expanded bytes
            else if (f32unit && f32mant0)     { c = 2; }           // f32 e8m0 scales
            else if (bfunit && bfpow2)        { c = 2; bf = 1; }   // bf16 e8m0 scales
            else if (f32unit)                 { c = 1; }           // f32 softmax weights
            else if (bfunit)                  { c = 1; bf = 1; }   // bf16 softmax weights
            else if (f32small && neg32 && pos32) { c = 3; }        // f32 hidden
            else if (bfsmall && negB && posB)    { c = 3; bf = 1; }// bf16 hidden
            else                              { c = 4; bf = 0; }   // packed uint8
            cls[w] = c; bff[w] = bf; ssz[w] = in.sz[w];
        }
    }
    __syncthreads();
    if (threadIdx.x == 0) {
        int ix = -1, ii = -1, iw = -1, s1 = -1, s2 = -1, p1 = -1, p2 = -1;
        for (int i = 0; i < in.n && i < 8; i++) {
            switch (cls[i]) {
                case 0: ii = i; break;
                case 1: iw = i; break;
                case 2: if (s1 < 0) s1 = i; else s2 = i; break;
                case 3: ix = i; break;
                case 4: if (p1 < 0) p1 = i; else p2 = i; break;
                default: break;
            }
        }
        if (ix >= 0 && ii >= 0 && iw >= 0 && s2 >= 0 && p2 >= 0) {
            int gus_i = s1, dsc_i = s2;
            if (ssz[s2] > ssz[s1]) { gus_i = s2; dsc_i = s1; }
            int guw_i = p1, dwn_i = p2;
            if (ssz[p2] > ssz[p1]) { guw_i = p2; dwn_i = p1; }
            g_rp[0] = in.p[ix];    g_bf[0] = bff[ix];
            g_rp[1] = in.p[ii];    g_bf[1] = bff[ii];
            g_rp[2] = in.p[iw];    g_bf[2] = bff[iw];
            g_rp[3] = in.p[guw_i]; g_bf[3] = bff[guw_i];
            g_rp[4] = in.p[gus_i]; g_bf[4] = bff[gus_i];
            g_rp[5] = in.p[dwn_i]; g_bf[5] = bff[dwn_i];
            g_rp[6] = in.p[dsc_i]; g_bf[6] = bff[dsc_i];
            g_bf[7] = bff[ix];
        } else {
            g_rp[0] = in.p[0]; g_rp[2] = in.p[1]; g_rp[1] = in.p[2];
            g_rp[3] = in.p[3]; g_rp[4] = in.p[4]; g_rp[5] = in.p[5]; g_rp[6] = in.p[6];
            for (int i = 0; i < 8; i++) g_bf[i] = 0;
        }
    }
}

// ---------------- helpers ----------------
__device__ __forceinline__ float ldf(const void* p, int bf, size_t i) {
    return bf ? __bfloat162float(((const __nv_bfloat16*)p)[i]) : ((const float*)p)[i];
}
__device__ __forceinline__ int ldid(const void* p, int flag, int i) {
    if (flag == 2) return (int)((const long long*)p)[i];
    if (flag == 3) return (int)((const float*)p)[i];
    return ((const int*)p)[i];
}
// read logical byte i of a weight tensor under any materialization
__device__ __forceinline__ unsigned ldb(const void* p, int m, size_t i) {
    switch (m) {
        case 3:  return ((const unsigned*)p)[i] & 255u;
        case 4:  return (unsigned)((const float*)p)[i] & 255u;
        case 5:  return (unsigned)(((const unsigned long long*)p)[i] & 255ull);
        default: return ((const uint8_t*)p)[i];
    }
}
__device__ __forceinline__ float fp4v(unsigned n) {
    float m = (float)((0xC8643210u >> ((n & 7u) * 4)) & 15u);
    return (n & 8u) ? -m : m;
}

// ---------------- one-time weight repack into packed uint8 scratch ----------------
__global__ void k_repack(uint8_t* __restrict__ dst, int rpIdx, size_t nbytes) {
    size_t i = (size_t)blockIdx.x * 256 + threadIdx.x;   // one uint32 (4 bytes) per thread
    if (i * 4 >= nbytes) return;
    const void* p = g_rp[rpIdx];
    const int m = g_bf[rpIdx];
    unsigned v;
    if (m == 0) {
        v = ((const unsigned*)p)[i];
    } else {
        size_t b = i * 4;
        v = ldb(p, m, b) | (ldb(p, m, b + 1) << 8) |
            (ldb(p, m, b + 2) << 16) | (ldb(p, m, b + 3) << 24);
    }
    ((unsigned*)dst)[i] = v;
}

// ---------------- stage 1: act[s, f] = silu(x·Wg)·(x·Wu)·w ----------------
__global__ void __launch_bounds__(256) k_act() {
    const void* xp  = g_rp[0]; const int xbf = g_bf[0];
    const void* idp = g_rp[1];
    const void* wtp = g_rp[2]; const int wbf = g_bf[2];
    const void* Sp  = g_rp[4]; const int sbf = g_bf[4];
    const uint8_t* W = g_guw;

    const int f = blockIdx.x * 256 + threadIdx.x;
    const int s = blockIdx.y;
    const int t = s >> 2;
    const int e = ldid(idp, g_bf[1], s) & (NEXP - 1);
    const float w = ldf(wtp, wbf, s);

    const uint8_t* wg = W + ((size_t)e * 2 * F_DIM + f) * (H_DIM / 2);
    const uint8_t* wu = W + ((size_t)e * 2 * F_DIM + F_DIM + f) * (H_DIM / 2);
    const size_t sgB = ((size_t)e * 2 * F_DIM + f) * (H_DIM / 32);
    const size_t suB = ((size_t)e * 2 * F_DIM + F_DIM + f) * (H_DIM / 32);

    float accG = 0.f, accU = 0.f;
    for (int grp = 0; grp < H_DIM / 32; ++grp) {
        const float sg = ldf(Sp, sbf, sgB + grp) * 0.5f;
        const float su = ldf(Sp, sbf, suB + grp) * 0.5f;
        const uint4 pg = *(const uint4*)(wg + grp * 16);
        const uint4 pu = *(const uint4*)(wu + grp * 16);
        const unsigned gw[4] = {pg.x, pg.y, pg.z, pg.w};
        const unsigned uw[4] = {pu.x, pu.y, pu.z, pu.w};
        float dg = 0.f, du = 0.f;
        #pragma unroll
        for (int b = 0; b < 4; b++) {
            #pragma unroll
            for (int j = 0; j < 4; j++) {
                const unsigned bg = (gw[b] >> (8 * j)) & 255u;
                const unsigned bu = (uw[b] >> (8 * j)) & 255u;
                const int h = grp * 32 + b * 8 + j * 2;
                const float x0 = ldf(xp, xbf, (size_t)t * H_DIM + h);
                const float x1 = ldf(xp, xbf, (size_t)t * H_DIM + h + 1);
                dg += fp4v(bg & 15u) * x0 + fp4v(bg >> 4) * x1;
                du += fp4v(bu & 15u) * x0 + fp4v(bu >> 4) * x1;
            }
        }
        accG = fmaf(dg, sg, accG);
        accU = fmaf(du, su, accU);
    }
    const float sig = 1.f / (1.f + __expf(-accG));
    g_act[(size_t)s * F_DIM + f] = accG * sig * accU * w;
}

// ---------------- stage 2: out[t, h] = sum_k act[s,:]·Wd[e_k, h, :] ----------------
__global__ void __launch_bounds__(256) k_out(void* __restrict__ outv) {
    const void* idp = g_rp[1];
    const void* Sp  = g_rp[6]; const int sbf = g_bf[6];
    const uint8_t* W = g_dwn;

    const int h = blockIdx.x * 256 + threadIdx.x;
    const int t = blockIdx.y;

    float acc = 0.f;
    #pragma unroll
    for (int k = 0; k < TOPK; k++) {
        const int s = t * TOPK + k;
        const int e = ldid(idp, g_bf[1], s) & (NEXP - 1);
        const uint8_t* wd = W + ((size_t)e * H_DIM + h) * (F_DIM / 2);
        const size_t sB   = ((size_t)e * H_DIM + h) * (F_DIM / 32);
        const float* arow = g_act + (size_t)s * F_DIM;
        for (int grp = 0; grp < F_DIM / 32; ++grp) {
            const float sc = ldf(Sp, sbf, sB + grp) * 0.5f;
            const uint4 pv = *(const uint4*)(wd + grp * 16);
            const unsigned ww[4] = {pv.x, pv.y, pv.z, pv.w};
            float d = 0.f;
            #pragma unroll
            for (int b = 0; b < 4; b++) {
                #pragma unroll
                for (int j = 0; j < 4; j++) {
                    const unsigned by = (ww[b] >> (8 * j)) & 255u;
                    const int f = grp * 32 + b * 8 + j * 2;
                    d += fp4v(by & 15u) * arow[f] + fp4v(by >> 4) * arow[f + 1];
                }
            }
            acc = fmaf(d, sc, acc);
        }
    }
    if (g_bf[7])
        ((__nv_bfloat16*)outv)[(size_t)t * H_DIM + h] = __float2bfloat16(acc);
    else
        ((float*)outv)[(size_t)t * H_DIM + h] = acc;
}

extern "C" void kernel_launch(void* const* d_in, const int* in_sizes, int n_in,
                              void* d_out, int out_size) {
    InPtrs in;
    int n = (n_in < 8) ? n_in : 8;
    for (int i = 0; i < 8; i++) {
        in.p[i]  = (i < n) ? d_in[i] : nullptr;
        in.sz[i] = (i < n) ? (long long)in_sizes[i] : 0;
    }
    in.n = n;

    uint8_t* guw = nullptr; cudaGetSymbolAddress((void**)&guw, g_guw);
    uint8_t* dwn = nullptr; cudaGetSymbolAddress((void**)&dwn, g_dwn);

    const size_t GU_BYTES = (size_t)NEXP * 2 * F_DIM * (H_DIM / 2);   // 33554432
    const size_t DW_BYTES = (size_t)NEXP * H_DIM * (F_DIM / 2);       // 16777216

    k_resolve<<<1, 256>>>(in);
    k_repack<<<(unsigned)((GU_BYTES / 4 + 255) / 256), 256>>>(guw, 3, GU_BYTES);
    k_repack<<<(unsigned)((DW_BYTES / 4 + 255) / 256), 256>>>(dwn, 5, DW_BYTES);
    k_act<<<dim3(F_DIM / 256, NSLOT), 256>>>();
    k_out<<<dim3(H_DIM / 256, T_TOK), 256>>>(d_out);
}

// round 9
// speedup vs baseline: 5.5211x; 5.5211x over previous
#include <cuda_runtime.h>
#include <cuda_bf16.h>
#include <cstdint>

#define T_TOK 2048
#define H_DIM 2048
#define F_DIM 1024
#define NEXP  16
#define TOPK  4
#define NSLOT (T_TOK * TOPK)   // 8192

// ---------------- device scratch ----------------
__device__ int     g_cnt[NEXP];
__device__ int     g_slot[NEXP * NSLOT];
__device__ float   g_wt[NEXP * NSLOT];
__device__ float   g_act[(size_t)NSLOT * F_DIM];                    // 32 MB
__device__ float   g_part[(size_t)NSLOT * H_DIM];                   // 64 MB
__device__ uint8_t g_guw[(size_t)NEXP * 2 * F_DIM * (H_DIM / 2)];   // 33.5 MB packed
__device__ uint8_t g_dwn[(size_t)NEXP * H_DIM * (F_DIM / 2)];       // 16.8 MB packed

// resolved pointers: 0=x 1=ids 2=wts 3=guw 4=gus 5=dwn 6=dsc
__device__ const void* g_rp[7];
// dtype flags: float-ish slots {0,2,4,6}: 0=f32 1=bf16. ids slot 1: 0=i32 2=i64 3=f32.
// weight slots {3,5}: 0=packed u8, 3=int32 bytes, 4=f32 bytes, 5=int64 bytes. [7]=out bf16.
__device__ int g_bf[8];

struct InPtrs { const void* p[8]; long long sz[8]; int n; };

__device__ __forceinline__ float bfh(unsigned h) { return __uint_as_float(h << 16); }

// ---------------- content+dtype based input resolution (proven in R8) ----------------
__global__ void k_resolve(InPtrs in) {
    __shared__ int cls[8], bff[8];
    __shared__ long long ssz[8];
    int w = threadIdx.x >> 5, lane = threadIdx.x & 31;
    if (w < 8 && lane == 0) { cls[w] = -1; bff[w] = 0; ssz[w] = 0; }
    __syncthreads();
    if (w < in.n && w < 8) {
        const unsigned* u = (const unsigned*)in.p[w];
        bool lt16 = true, i64ids = true, i64b = true, u32b = true;
        bool fint16 = true, fint256 = true;
        bool f32unit = true, f32mant0 = true, f32small = true;
        bool bfunit = true, bfpow2 = true, bfsmall = true;
        bool neg32 = false, pos32 = false, negB = false, posB = false;
        #pragma unroll
        for (int j = 0; j < 4; j++) {
            int idx = lane + 32 * j;
            unsigned v = u[idx];
            lt16   &= (v < 16u);
            i64ids &= (idx & 1) ? (v == 0u) : (v < 16u);
            i64b   &= (idx & 1) ? (v == 0u) : (v < 256u);
            u32b   &= (v < 256u);
            float f = __uint_as_float(v);
            unsigned ex = (v >> 23) & 255u;
            bool fin = (ex != 255u);
            bool isint = fin && f >= 0.f && f == floorf(f);
            fint16  &= (isint && f < 16.f);
            fint256 &= (isint && f < 256.f);
            f32unit  &= (fin && f > 0.f && f < 1.f);
            f32mant0 &= ((v & 0x7FFFFFu) == 0u);
            f32small &= (fin && fabsf(f) < 100.f);
            neg32 |= (f < 0.f); pos32 |= (f > 0.f);
            unsigned hs[2] = { v >> 16, v & 0xFFFFu };
            #pragma unroll
            for (int q = 0; q < 2; q++) {
                unsigned h = hs[q];
                float fb = bfh(h);
                bool finB = (((h >> 7) & 255u) != 255u);
                bfunit  &= (finB && fb > 0.f && fb < 1.f);
                bfpow2  &= (finB && fb > 0.f && fb < 1.f && ((h & 127u) == 0u));
                bfsmall &= (finB && fabsf(fb) < 100.f);
                negB |= (fb < 0.f); posB |= (fb > 0.f);
            }
        }
        unsigned full = ~0u;
        lt16 = __all_sync(full, lt16);       i64ids = __all_sync(full, i64ids);
        i64b = __all_sync(full, i64b);       u32b = __all_sync(full, u32b);
        fint16 = __all_sync(full, fint16);   fint256 = __all_sync(full, fint256);
        f32unit = __all_sync(full, f32unit); f32mant0 = __all_sync(full, f32mant0);
        f32small = __all_sync(full, f32small);
        bfunit = __all_sync(full, bfunit);   bfpow2 = __all_sync(full, bfpow2);
        bfsmall = __all_sync(full, bfsmall);
        neg32 = __any_sync(full, neg32);     pos32 = __any_sync(full, pos32);
        negB = __any_sync(full, negB);       posB = __any_sync(full, posB);
        if (lane == 0) {
            int c, bf = 0;
            if (lt16)                         { c = 0; }
            else if (i64ids)                  { c = 0; bf = 2; }
            else if (fint16)                  { c = 0; bf = 3; }
            else if (i64b)                    { c = 4; bf = 5; }
            else if (u32b)                    { c = 4; bf = 3; }
            else if (fint256)                 { c = 4; bf = 4; }
            else if (f32unit && f32mant0)     { c = 2; }
            else if (bfunit && bfpow2)        { c = 2; bf = 1; }
            else if (f32unit)                 { c = 1; }
            else if (bfunit)                  { c = 1; bf = 1; }
            else if (f32small && neg32 && pos32) { c = 3; }
            else if (bfsmall && negB && posB)    { c = 3; bf = 1; }
            else                              { c = 4; bf = 0; }
            cls[w] = c; bff[w] = bf; ssz[w] = in.sz[w];
        }
    }
    __syncthreads();
    if (threadIdx.x == 0) {
        int ix = -1, ii = -1, iw = -1, s1 = -1, s2 = -1, p1 = -1, p2 = -1;
        for (int i = 0; i < in.n && i < 8; i++) {
            switch (cls[i]) {
                case 0: ii = i; break;
                case 1: iw = i; break;
                case 2: if (s1 < 0) s1 = i; else s2 = i; break;
                case 3: ix = i; break;
                case 4: if (p1 < 0) p1 = i; else p2 = i; break;
                default: break;
            }
        }
        if (ix >= 0 && ii >= 0 && iw >= 0 && s2 >= 0 && p2 >= 0) {
            int gus_i = s1, dsc_i = s2;
            if (ssz[s2] > ssz[s1]) { gus_i = s2; dsc_i = s1; }
            int guw_i = p1, dwn_i = p2;
            if (ssz[p2] > ssz[p1]) { guw_i = p2; dwn_i = p1; }
            g_rp[0] = in.p[ix];    g_bf[0] = bff[ix];
            g_rp[1] = in.p[ii];    g_bf[1] = bff[ii];
            g_rp[2] = in.p[iw];    g_bf[2] = bff[iw];
            g_rp[3] = in.p[guw_i]; g_bf[3] = bff[guw_i];
            g_rp[4] = in.p[gus_i]; g_bf[4] = bff[gus_i];
            g_rp[5] = in.p[dwn_i]; g_bf[5] = bff[dwn_i];
            g_rp[6] = in.p[dsc_i]; g_bf[6] = bff[dsc_i];
            g_bf[7] = bff[ix];
        } else {
            g_rp[0] = in.p[0]; g_rp[2] = in.p[1]; g_rp[1] = in.p[2];
            g_rp[3] = in.p[3]; g_rp[4] = in.p[4]; g_rp[5] = in.p[5]; g_rp[6] = in.p[6];
            for (int i = 0; i < 8; i++) g_bf[i] = 0;
        }
        for (int e = 0; e < NEXP; e++) g_cnt[e] = 0;
    }
}

// ---------------- helpers ----------------
__device__ __forceinline__ float ldf(const void* p, int bf, size_t i) {
    return bf ? __bfloat162float(((const __nv_bfloat16*)p)[i]) : ((const float*)p)[i];
}
__device__ __forceinline__ int ldid(const void* p, int flag, int i) {
    if (flag == 2) return (int)((const long long*)p)[i];
    if (flag == 3) return (int)((const float*)p)[i];
    return ((const int*)p)[i];
}
__device__ __forceinline__ unsigned ldb(const void* p, int m, size_t i) {
    switch (m) {
        case 3:  return ((const unsigned*)p)[i] & 255u;
        case 4:  return (unsigned)((const float*)p)[i] & 255u;
        case 5:  return (unsigned)(((const unsigned long long*)p)[i] & 255ull);
        default: return ((const uint8_t*)p)[i];
    }
}
// e2m1 magnitudes *2 packed as hex digits; caller folds *0.5 into scale
__device__ __forceinline__ float fp4v(unsigned n) {
    float m = (float)((0xC8643210u >> ((n & 7u) * 4)) & 15u);
    return (n & 8u) ? -m : m;
}

// ---------------- one-time weight repack into packed uint8 scratch ----------------
__global__ void k_repack(uint8_t* __restrict__ dst, int rpIdx, size_t nbytes) {
    size_t i = (size_t)blockIdx.x * 256 + threadIdx.x;
    if (i * 4 >= nbytes) return;
    const void* p = g_rp[rpIdx];
    const int m = g_bf[rpIdx];
    unsigned v;
    if (m == 0) {
        v = ((const unsigned*)p)[i];
    } else {
        size_t b = i * 4;
        v = ldb(p, m, b) | (ldb(p, m, b + 1) << 8) |
            (ldb(p, m, b + 2) << 16) | (ldb(p, m, b + 3) << 24);
    }
    ((unsigned*)dst)[i] = v;
}

// ---------------- routing ----------------
__global__ void k_route() {
    int s = blockIdx.x * 256 + threadIdx.x;
    if (s >= NSLOT) return;
    int e = ldid(g_rp[1], g_bf[1], s) & (NEXP - 1);
    int p = atomicAdd(&g_cnt[e], 1);
    g_slot[e * NSLOT + p] = s;
    g_wt[e * NSLOT + p]   = ldf(g_rp[2], g_bf[2], s);
}

// GEMM1: act[slot, f] = silu(x@Wg) * (x@Wu) * route_w. Tiles BM=64, BN=64, BK=32.
__global__ void __launch_bounds__(256) k_gemm1() {
    const void* xp  = g_rp[0]; const int xbf = g_bf[0];
    const void* Sp  = g_rp[4]; const int sbf = g_bf[4];
    const uint8_t* W = g_guw;

    const int e   = blockIdx.z;
    const int cnt = g_cnt[e];
    const int m0  = blockIdx.y * 64;
    if (m0 >= cnt) return;
    const int n0  = blockIdx.x * 64;

    __shared__ float As[32][64];
    __shared__ float Bg[32][64];
    __shared__ float Bu[32][64];
    __shared__ int   sSlot[64];
    __shared__ int   sTok[64];
    __shared__ float sWt[64];

    const int tid = threadIdx.x;
    if (tid < 64) {
        int m = m0 + tid;
        int slot = (m < cnt) ? g_slot[e * NSLOT + m] : g_slot[e * NSLOT];
        sSlot[tid] = slot;
        sTok[tid]  = slot >> 2;
        sWt[tid]   = (m < cnt) ? g_wt[e * NSLOT + m] : 0.f;
    }
    __syncthreads();

    // A loaders: 256 threads, each covers 8 columns of one row per tile
    const int aRow = tid & 63;
    const int aC4  = tid >> 6;
    const size_t xBase = (size_t)sTok[aRow] * H_DIM;

    // B loaders: threads 0..63 gate rows, 64..127 up rows
    const bool bActive = tid < 128;
    const int  isUp = (tid >> 6) & 1;
    const int  bn   = tid & 63;
    const uint8_t* wrow = nullptr;
    size_t sBase = 0;
    if (bActive) {
        int row = (isUp ? F_DIM : 0) + n0 + bn;
        wrow  = W + ((size_t)e * 2 * F_DIM + row) * (H_DIM / 2);
        sBase = ((size_t)e * 2 * F_DIM + row) * (H_DIM / 32);
    }

    const int tn = tid & 15, tm = tid >> 4;
    float cg[4][4] = {}, cu[4][4] = {};

    for (int kc = 0; kc < H_DIM / 32; ++kc) {
        const int h0 = kc * 32;
        float a0[4], a1[4];
        {
            int c0 = h0 + aC4 * 4, c1 = h0 + (aC4 + 4) * 4;
            #pragma unroll
            for (int q = 0; q < 4; q++) {
                a0[q] = ldf(xp, xbf, xBase + c0 + q);
                a1[q] = ldf(xp, xbf, xBase + c1 + q);
            }
        }
        uint4 pv = make_uint4(0, 0, 0, 0);
        float sc = 0.f;
        if (bActive) {
            pv = *(const uint4*)(wrow + h0 / 2);
            sc = ldf(Sp, sbf, sBase + kc) * 0.5f;
        }
        __syncthreads();   // previous tile's compute done
        {
            int k0 = aC4 * 4, k1 = (aC4 + 4) * 4;
            #pragma unroll
            for (int q = 0; q < 4; q++) {
                As[k0 + q][aRow] = a0[q];
                As[k1 + q][aRow] = a1[q];
            }
        }
        if (bActive) {
            float* Bd = isUp ? &Bu[0][0] : &Bg[0][0];
            unsigned wds[4] = {pv.x, pv.y, pv.z, pv.w};
            #pragma unroll
            for (int b = 0; b < 4; b++) {
                unsigned wd = wds[b];
                #pragma unroll
                for (int j = 0; j < 4; j++) {
                    unsigned byte = (wd >> (8 * j)) & 255u;
                    int k = b * 8 + j * 2;
                    Bd[(k + 0) * 64 + bn] = fp4v(byte & 15u) * sc;
                    Bd[(k + 1) * 64 + bn] = fp4v(byte >> 4)  * sc;
                }
            }
        }
        __syncthreads();
        #pragma unroll
        for (int k = 0; k < 32; k++) {
            float4 av = *(const float4*)&As[k][tm * 4];
            float4 gv = *(const float4*)&Bg[k][tn * 4];
            float4 uv = *(const float4*)&Bu[k][tn * 4];
            float aa[4] = {av.x, av.y, av.z, av.w};
            float gg[4] = {gv.x, gv.y, gv.z, gv.w};
            float uu[4] = {uv.x, uv.y, uv.z, uv.w};
            #pragma unroll
            for (int i = 0; i < 4; i++)
                #pragma unroll
                for (int j = 0; j < 4; j++) {
                    cg[i][j] = fmaf(aa[i], gg[j], cg[i][j]);
                    cu[i][j] = fmaf(aa[i], uu[j], cu[i][j]);
                }
        }
    }

    #pragma unroll
    for (int i = 0; i < 4; i++) {
        int mi = tm * 4 + i;
        if (m0 + mi < cnt) {
            int slot = sSlot[mi];
            float wgt = sWt[mi];
            float4 o;
            float* po = &o.x;
            #pragma unroll
            for (int j = 0; j < 4; j++) {
                float g = cg[i][j], u = cu[i][j];
                float sg = 1.f / (1.f + __expf(-g));
                po[j] = g * sg * u * wgt;
            }
            *(float4*)(g_act + (size_t)slot * F_DIM + n0 + tn * 4) = o;
        }
    }
}

// GEMM2: part[slot, h] = act[slot,:] @ Wd[e,h,:]
__global__ void __launch_bounds__(256) k_gemm2() {
    const void* Sp = g_rp[6]; const int sbf = g_bf[6];
    const uint8_t* W = g_dwn;

    const int e   = blockIdx.z;
    const int cnt = g_cnt[e];
    const int m0  = blockIdx.y * 64;
    if (m0 >= cnt) return;
    const int n0  = blockIdx.x * 64;

    __shared__ float As[32][64];
    __shared__ float Bs[32][64];
    __shared__ int   sSlot[64];

    const int tid = threadIdx.x;
    if (tid < 64) {
        int m = m0 + tid;
        sSlot[tid] = (m < cnt) ? g_slot[e * NSLOT + m] : g_slot[e * NSLOT];
    }
    __syncthreads();

    const int aRow = tid & 63;
    const int aC4  = tid >> 6;
    const float* arow = g_act + (size_t)sSlot[aRow] * F_DIM;

    const bool bActive = tid < 64;
    const int  bn = tid & 63;
    const uint8_t* wrow = nullptr;
    size_t sBase = 0;
    if (bActive) {
        int row = n0 + bn;
        wrow  = W + ((size_t)e * H_DIM + row) * (F_DIM / 2);
        sBase = ((size_t)e * H_DIM + row) * (F_DIM / 32);
    }

    const int tn = tid & 15, tm = tid >> 4;
    float c[4][4] = {};

    for (int kc = 0; kc < F_DIM / 32; ++kc) {
        const int f0 = kc * 32;
        float4 a0 = *(const float4*)(arow + f0 + aC4 * 4);
        float4 a1 = *(const float4*)(arow + f0 + (aC4 + 4) * 4);
        uint4 pv = make_uint4(0, 0, 0, 0);
        float sc = 0.f;
        if (bActive) {
            pv = *(const uint4*)(wrow + f0 / 2);
            sc = ldf(Sp, sbf, sBase + kc) * 0.5f;
        }
        __syncthreads();
        {
            int k0 = aC4 * 4, k1 = (aC4 + 4) * 4;
            As[k0 + 0][aRow] = a0.x; As[k0 + 1][aRow] = a0.y;
            As[k0 + 2][aRow] = a0.z; As[k0 + 3][aRow] = a0.w;
            As[k1 + 0][aRow] = a1.x; As[k1 + 1][aRow] = a1.y;
            As[k1 + 2][aRow] = a1.z; As[k1 + 3][aRow] = a1.w;
        }
        if (bActive) {
            unsigned wds[4] = {pv.x, pv.y, pv.z, pv.w};
            #pragma unroll
            for (int b = 0; b < 4; b++) {
                unsigned wd = wds[b];
                #pragma unroll
                for (int j = 0; j < 4; j++) {
                    unsigned byte = (wd >> (8 * j)) & 255u;
                    int k = b * 8 + j * 2;
                    Bs[k + 0][bn] = fp4v(byte & 15u) * sc;
                    Bs[k + 1][bn] = fp4v(byte >> 4)  * sc;
                }
            }
        }
        __syncthreads();
        #pragma unroll
        for (int k = 0; k < 32; k++) {
            float4 av = *(const float4*)&As[k][tm * 4];
            float4 bv = *(const float4*)&Bs[k][tn * 4];
            float aa[4] = {av.x, av.y, av.z, av.w};
            float bb[4] = {bv.x, bv.y, bv.z, bv.w};
            #pragma unroll
            for (int i = 0; i < 4; i++)
                #pragma unroll
                for (int j = 0; j < 4; j++)
                    c[i][j] = fmaf(aa[i], bb[j], c[i][j]);
        }
    }

    #pragma unroll
    for (int i = 0; i < 4; i++) {
        int mi = tm * 4 + i;
        if (m0 + mi < cnt) {
            int slot = sSlot[mi];
            float4 o = make_float4(c[i][0], c[i][1], c[i][2], c[i][3]);
            *(float4*)(g_part + (size_t)slot * H_DIM + n0 + tn * 4) = o;
        }
    }
}

// deterministic 4-way reduce; dtype-flexible output
__global__ void k_reduce(void* __restrict__ outv) {
    int idx = blockIdx.x * 256 + threadIdx.x;
    int t = idx / (H_DIM / 4);
    int c = idx % (H_DIM / 4);
    const float4* p = (const float4*)g_part;
    float4 a = p[(size_t)(t * 4 + 0) * (H_DIM / 4) + c];
    float4 b = p[(size_t)(t * 4 + 1) * (H_DIM / 4) + c];
    float4 d = p[(size_t)(t * 4 + 2) * (H_DIM / 4) + c];
    float4 e = p[(size_t)(t * 4 + 3) * (H_DIM / 4) + c];
    float s0 = a.x + b.x + d.x + e.x, s1 = a.y + b.y + d.y + e.y;
    float s2 = a.z + b.z + d.z + e.z, s3 = a.w + b.w + d.w + e.w;
    if (g_bf[7]) {
        __nv_bfloat16* ob = (__nv_bfloat16*)outv;
        size_t base = (size_t)t * H_DIM + c * 4;
        ob[base + 0] = __float2bfloat16(s0);
        ob[base + 1] = __float2bfloat16(s1);
        ob[base + 2] = __float2bfloat16(s2);
        ob[base + 3] = __float2bfloat16(s3);
    } else {
        ((float4*)outv)[(size_t)t * (H_DIM / 4) + c] = make_float4(s0, s1, s2, s3);
    }
}

extern "C" void kernel_launch(void* const* d_in, const int* in_sizes, int n_in,
                              void* d_out, int out_size) {
    InPtrs in;
    int n = (n_in < 8) ? n_in : 8;
    for (int i = 0; i < 8; i++) {
        in.p[i]  = (i < n) ? d_in[i] : nullptr;
        in.sz[i] = (i < n) ? (long long)in_sizes[i] : 0;
    }
    in.n = n;

    uint8_t* guw = nullptr; cudaGetSymbolAddress((void**)&guw, g_guw);
    uint8_t* dwn = nullptr; cudaGetSymbolAddress((void**)&dwn, g_dwn);

    const size_t GU_BYTES = (size_t)NEXP * 2 * F_DIM * (H_DIM / 2);
    const size_t DW_BYTES = (size_t)NEXP * H_DIM * (F_DIM / 2);

    k_resolve<<<1, 256>>>(in);
    k_repack<<<(unsigned)((GU_BYTES / 4 + 255) / 256), 256>>>(guw, 3, GU_BYTES);
    k_repack<<<(unsigned)((DW_BYTES / 4 + 255) / 256), 256>>>(dwn, 5, DW_BYTES);
    k_route<<<NSLOT / 256, 256>>>();
    k_gemm1<<<dim3(F_DIM / 64, NSLOT / 64, NEXP), 256>>>();
    k_gemm2<<<dim3(H_DIM / 64, NSLOT / 64, NEXP), 256>>>();
    k_reduce<<<(T_TOK * H_DIM / 4) / 256, 256>>>(d_out);
}

// round 10
// speedup vs baseline: 5.5348x; 1.0025x over previous
#include <cuda_runtime.h>
#include <cuda_bf16.h>
#include <cstdint>

#define T_TOK 2048
#define H_DIM 2048
#define F_DIM 1024
#define NEXP  16
#define TOPK  4
#define NSLOT (T_TOK * TOPK)   // 8192

// ---------------- device scratch ----------------
__device__ int     g_cnt[NEXP];
__device__ int     g_slot[NEXP * NSLOT];
__device__ float   g_wt[NEXP * NSLOT];
__device__ float   g_act[(size_t)NSLOT * F_DIM];                    // 32 MB
__device__ float   g_part[(size_t)NSLOT * H_DIM];                   // 64 MB
__device__ uint8_t g_guw[(size_t)NEXP * 2 * F_DIM * (H_DIM / 2)];   // 33.5 MB packed
__device__ uint8_t g_dwn[(size_t)NEXP * H_DIM * (F_DIM / 2)];       // 16.8 MB packed

// resolved pointers: 0=x 1=ids 2=wts 3=guw 4=gus 5=dwn 6=dsc
__device__ const void* g_rp[7];
// dtype flags: float-ish slots {0,2,4,6}: 0=f32 1=bf16. ids slot 1: 0=i32 2=i64 3=f32.
// weight slots {3,5}: 0=packed u8, 3=int32 bytes, 4=f32 bytes, 5=int64 bytes. [7]=out bf16.
__device__ int g_bf[8];

struct InPtrs { const void* p[8]; long long sz[8]; int n; };

__device__ __forceinline__ float bfh(unsigned h) { return __uint_as_float(h << 16); }

// ---------------- content+dtype based input resolution (proven in R8) ----------------
__global__ void k_resolve(InPtrs in) {
    __shared__ int cls[8], bff[8];
    __shared__ long long ssz[8];
    int w = threadIdx.x >> 5, lane = threadIdx.x & 31;
    if (w < 8 && lane == 0) { cls[w] = -1; bff[w] = 0; ssz[w] = 0; }
    __syncthreads();
    if (w < in.n && w < 8) {
        const unsigned* u = (const unsigned*)in.p[w];
        bool lt16 = true, i64ids = true, i64b = true, u32b = true;
        bool fint16 = true, fint256 = true;
        bool f32unit = true, f32mant0 = true, f32small = true;
        bool bfunit = true, bfpow2 = true, bfsmall = true;
        bool neg32 = false, pos32 = false, negB = false, posB = false;
        #pragma unroll
        for (int j = 0; j < 4; j++) {
            int idx = lane + 32 * j;
            unsigned v = u[idx];
            lt16   &= (v < 16u);
            i64ids &= (idx & 1) ? (v == 0u) : (v < 16u);
            i64b   &= (idx & 1) ? (v == 0u) : (v < 256u);
            u32b   &= (v < 256u);
            float f = __uint_as_float(v);
            unsigned ex = (v >> 23) & 255u;
            bool fin = (ex != 255u);
            bool isint = fin && f >= 0.f && f == floorf(f);
            fint16  &= (isint && f < 16.f);
            fint256 &= (isint && f < 256.f);
            f32unit  &= (fin && f > 0.f && f < 1.f);
            f32mant0 &= ((v & 0x7FFFFFu) == 0u);
            f32small &= (fin && fabsf(f) < 100.f);
            neg32 |= (f < 0.f); pos32 |= (f > 0.f);
            unsigned hs[2] = { v >> 16, v & 0xFFFFu };
            #pragma unroll
            for (int q = 0; q < 2; q++) {
                unsigned h = hs[q];
                float fb = bfh(h);
                bool finB = (((h >> 7) & 255u) != 255u);
                bfunit  &= (finB && fb > 0.f && fb < 1.f);
                bfpow2  &= (finB && fb > 0.f && fb < 1.f && ((h & 127u) == 0u));
                bfsmall &= (finB && fabsf(fb) < 100.f);
                negB |= (fb < 0.f); posB |= (fb > 0.f);
            }
        }
        unsigned full = ~0u;
        lt16 = __all_sync(full, lt16);       i64ids = __all_sync(full, i64ids);
        i64b = __all_sync(full, i64b);       u32b = __all_sync(full, u32b);
        fint16 = __all_sync(full, fint16);   fint256 = __all_sync(full, fint256);
        f32unit = __all_sync(full, f32unit); f32mant0 = __all_sync(full, f32mant0);
        f32small = __all_sync(full, f32small);
        bfunit = __all_sync(full, bfunit);   bfpow2 = __all_sync(full, bfpow2);
        bfsmall = __all_sync(full, bfsmall);
        neg32 = __any_sync(full, neg32);     pos32 = __any_sync(full, pos32);
        negB = __any_sync(full, negB);       posB = __any_sync(full, posB);
        if (lane == 0) {
            int c, bf = 0;
            if (lt16)                         { c = 0; }
            else if (i64ids)                  { c = 0; bf = 2; }
            else if (fint16)                  { c = 0; bf = 3; }
            else if (i64b)                    { c = 4; bf = 5; }
            else if (u32b)                    { c = 4; bf = 3; }
            else if (fint256)                 { c = 4; bf = 4; }
            else if (f32unit && f32mant0)     { c = 2; }
            else if (bfunit && bfpow2)        { c = 2; bf = 1; }
            else if (f32unit)                 { c = 1; }
            else if (bfunit)                  { c = 1; bf = 1; }
            else if (f32small && neg32 && pos32) { c = 3; }
            else if (bfsmall && negB && posB)    { c = 3; bf = 1; }
            else                              { c = 4; bf = 0; }
            cls[w] = c; bff[w] = bf; ssz[w] = in.sz[w];
        }
    }
    __syncthreads();
    if (threadIdx.x == 0) {
        int ix = -1, ii = -1, iw = -1, s1 = -1, s2 = -1, p1 = -1, p2 = -1;
        for (int i = 0; i < in.n && i < 8; i++) {
            switch (cls[i]) {
                case 0: ii = i; break;
                case 1: iw = i; break;
                case 2: if (s1 < 0) s1 = i; else s2 = i; break;
                case 3: ix = i; break;
                case 4: if (p1 < 0) p1 = i; else p2 = i; break;
                default: break;
            }
        }
        if (ix >= 0 && ii >= 0 && iw >= 0 && s2 >= 0 && p2 >= 0) {
            int gus_i = s1, dsc_i = s2;
            if (ssz[s2] > ssz[s1]) { gus_i = s2; dsc_i = s1; }
            int guw_i = p1, dwn_i = p2;
            if (ssz[p2] > ssz[p1]) { guw_i = p2; dwn_i = p1; }
            g_rp[0] = in.p[ix];    g_bf[0] = bff[ix];
            g_rp[1] = in.p[ii];    g_bf[1] = bff[ii];
            g_rp[2] = in.p[iw];    g_bf[2] = bff[iw];
            g_rp[3] = in.p[guw_i]; g_bf[3] = bff[guw_i];
            g_rp[4] = in.p[gus_i]; g_bf[4] = bff[gus_i];
            g_rp[5] = in.p[dwn_i]; g_bf[5] = bff[dwn_i];
            g_rp[6] = in.p[dsc_i]; g_bf[6] = bff[dsc_i];
            g_bf[7] = bff[ix];
        } else {
            g_rp[0] = in.p[0]; g_rp[2] = in.p[1]; g_rp[1] = in.p[2];
            g_rp[3] = in.p[3]; g_rp[4] = in.p[4]; g_rp[5] = in.p[5]; g_rp[6] = in.p[6];
            for (int i = 0; i < 8; i++) g_bf[i] = 0;
        }
        for (int e = 0; e < NEXP; e++) g_cnt[e] = 0;
    }
}

// ---------------- helpers ----------------
__device__ __forceinline__ float ldf(const void* p, int bf, size_t i) {
    return bf ? __bfloat162float(((const __nv_bfloat16*)p)[i]) : ((const float*)p)[i];
}
__device__ __forceinline__ int ldid(const void* p, int flag, int i) {
    if (flag == 2) return (int)((const long long*)p)[i];
    if (flag == 3) return (int)((const float*)p)[i];
    return ((const int*)p)[i];
}
__device__ __forceinline__ unsigned ldb(const void* p, int m, size_t i) {
    switch (m) {
        case 3:  return ((const unsigned*)p)[i] & 255u;
        case 4:  return (unsigned)((const float*)p)[i] & 255u;
        case 5:  return (unsigned)(((const unsigned long long*)p)[i] & 255ull);
        default: return ((const uint8_t*)p)[i];
    }
}
// e2m1 magnitudes *2 packed as hex digits; caller folds *0.5 into scale
__device__ __forceinline__ float fp4v(unsigned n) {
    float m = (float)((0xC8643210u >> ((n & 7u) * 4)) & 15u);
    return (n & 8u) ? -m : m;
}

// ---------------- one-time weight repack into packed uint8 scratch ----------------
__global__ void k_repack(uint8_t* __restrict__ dst, int rpIdx, size_t nbytes) {
    size_t i = (size_t)blockIdx.x * 256 + threadIdx.x;
    if (i * 4 >= nbytes) return;
    const void* p = g_rp[rpIdx];
    const int m = g_bf[rpIdx];
    unsigned v;
    if (m == 0) {
        v = ((const unsigned*)p)[i];
    } else {
        size_t b = i * 4;
        v = ldb(p, m, b) | (ldb(p, m, b + 1) << 8) |
            (ldb(p, m, b + 2) << 16) | (ldb(p, m, b + 3) << 24);
    }
    ((unsigned*)dst)[i] = v;
}

// ---------------- routing ----------------
__global__ void k_route() {
    int s = blockIdx.x * 256 + threadIdx.x;
    if (s >= NSLOT) return;
    int e = ldid(g_rp[1], g_bf[1], s) & (NEXP - 1);
    int p = atomicAdd(&g_cnt[e], 1);
    g_slot[e * NSLOT + p] = s;
    g_wt[e * NSLOT + p]   = ldf(g_rp[2], g_bf[2], s);
}

// GEMM1: act[slot, f] = silu(x@Wg) * (x@Wu) * route_w. Tiles BM=64, BN=64, BK=32.
__global__ void __launch_bounds__(256) k_gemm1() {
    const void* xp  = g_rp[0]; const int xbf = g_bf[0];
    const void* Sp  = g_rp[4]; const int sbf = g_bf[4];
    const uint8_t* W = g_guw;

    const int e   = blockIdx.z;
    const int cnt = g_cnt[e];
    const int m0  = blockIdx.y * 64;
    if (m0 >= cnt) return;
    const int n0  = blockIdx.x * 64;

    __shared__ float As[32][64];
    __shared__ float Bg[32][64];
    __shared__ float Bu[32][64];
    __shared__ int   sSlot[64];
    __shared__ int   sTok[64];
    __shared__ float sWt[64];

    const int tid = threadIdx.x;
    if (tid < 64) {
        int m = m0 + tid;
        int slot = (m < cnt) ? g_slot[e * NSLOT + m] : g_slot[e * NSLOT];
        sSlot[tid] = slot;
        sTok[tid]  = slot >> 2;
        sWt[tid]   = (m < cnt) ? g_wt[e * NSLOT + m] : 0.f;
    }
    __syncthreads();

    // A loaders: 256 threads, each covers 8 columns of one row per tile
    const int aRow = tid & 63;
    const int aC4  = tid >> 6;
    const size_t xBase = (size_t)sTok[aRow] * H_DIM;

    // B loaders: threads 0..63 gate rows, 64..127 up rows
    const bool bActive = tid < 128;
    const int  isUp = (tid >> 6) & 1;
    const int  bn   = tid & 63;
    const uint8_t* wrow = nullptr;
    size_t sBase = 0;
    if (bActive) {
        int row = (isUp ? F_DIM : 0) + n0 + bn;
        wrow  = W + ((size_t)e * 2 * F_DIM + row) * (H_DIM / 2);
        sBase = ((size_t)e * 2 * F_DIM + row) * (H_DIM / 32);
    }

    const int tn = tid & 15, tm = tid >> 4;
    float cg[4][4] = {}, cu[4][4] = {};

    for (int kc = 0; kc < H_DIM / 32; ++kc) {
        const int h0 = kc * 32;
        float a0[4], a1[4];
        {
            int c0 = h0 + aC4 * 4, c1 = h0 + (aC4 + 4) * 4;
            #pragma unroll
            for (int q = 0; q < 4; q++) {
                a0[q] = ldf(xp, xbf, xBase + c0 + q);
                a1[q] = ldf(xp, xbf, xBase + c1 + q);
            }
        }
        uint4 pv = make_uint4(0, 0, 0, 0);
        float sc = 0.f;
        if (bActive) {
            pv = *(const uint4*)(wrow + h0 / 2);
            sc = ldf(Sp, sbf, sBase + kc) * 0.5f;
        }
        __syncthreads();   // previous tile's compute done
        {
            int k0 = aC4 * 4, k1 = (aC4 + 4) * 4;
            #pragma unroll
            for (int q = 0; q < 4; q++) {
                As[k0 + q][aRow] = a0[q];
                As[k1 + q][aRow] = a1[q];
            }
        }
        if (bActive) {
            float* Bd = isUp ? &Bu[0][0] : &Bg[0][0];
            unsigned wds[4] = {pv.x, pv.y, pv.z, pv.w};
            #pragma unroll
            for (int b = 0; b < 4; b++) {
                unsigned wd = wds[b];
                #pragma unroll
                for (int j = 0; j < 4; j++) {
                    unsigned byte = (wd >> (8 * j)) & 255u;
                    int k = b * 8 + j * 2;
                    Bd[(k + 0) * 64 + bn] = fp4v(byte & 15u) * sc;
                    Bd[(k + 1) * 64 + bn] = fp4v(byte >> 4)  * sc;
                }
            }
        }
        __syncthreads();
        #pragma unroll
        for (int k = 0; k < 32; k++) {
            float4 av = *(const float4*)&As[k][tm * 4];
            float4 gv = *(const float4*)&Bg[k][tn * 4];
            float4 uv = *(const float4*)&Bu[k][tn * 4];
            float aa[4] = {av.x, av.y, av.z, av.w};
            float gg[4] = {gv.x, gv.y, gv.z, gv.w};
            float uu[4] = {uv.x, uv.y, uv.z, uv.w};
            #pragma unroll
            for (int i = 0; i < 4; i++)
                #pragma unroll
                for (int j = 0; j < 4; j++) {
                    cg[i][j] = fmaf(aa[i], gg[j], cg[i][j]);
                    cu[i][j] = fmaf(aa[i], uu[j], cu[i][j]);
                }
        }
    }

    #pragma unroll
    for (int i = 0; i < 4; i++) {
        int mi = tm * 4 + i;
        if (m0 + mi < cnt) {
            int slot = sSlot[mi];
            float wgt = sWt[mi];
            float4 o;
            float* po = &o.x;
            #pragma unroll
            for (int j = 0; j < 4; j++) {
                float g = cg[i][j], u = cu[i][j];
                float sg = 1.f / (1.f + __expf(-g));
                po[j] = g * sg * u * wgt;
            }
            *(float4*)(g_act + (size_t)slot * F_DIM + n0 + tn * 4) = o;
        }
    }
}

// GEMM2: part[slot, h] = act[slot,:] @ Wd[e,h,:]
__global__ void __launch_bounds__(256) k_gemm2() {
    const void* Sp = g_rp[6]; const int sbf = g_bf[6];
    const uint8_t* W = g_dwn;

    const int e   = blockIdx.z;
    const int cnt = g_cnt[e];
    const int m0  = blockIdx.y * 64;
    if (m0 >= cnt) return;
    const int n0  = blockIdx.x * 64;

    __shared__ float As[32][64];
    __shared__ float Bs[32][64];
    __shared__ int   sSlot[64];

    const int tid = threadIdx.x;
    if (tid < 64) {
        int m = m0 + tid;
        sSlot[tid] = (m < cnt) ? g_slot[e * NSLOT + m] : g_slot[e * NSLOT];
    }
    __syncthreads();

    const int aRow = tid & 63;
    const int aC4  = tid >> 6;
    const float* arow = g_act + (size_t)sSlot[aRow] * F_DIM;

    const bool bActive = tid < 64;
    const int  bn = tid & 63;
    const uint8_t* wrow = nullptr;
    size_t sBase = 0;
    if (bActive) {
        int row = n0 + bn;
        wrow  = W + ((size_t)e * H_DIM + row) * (F_DIM / 2);
        sBase = ((size_t)e * H_DIM + row) * (F_DIM / 32);
    }

    const int tn = tid & 15, tm = tid >> 4;
    float c[4][4] = {};

    for (int kc = 0; kc < F_DIM / 32; ++kc) {
        const int f0 = kc * 32;
        float4 a0 = *(const float4*)(arow + f0 + aC4 * 4);
        float4 a1 = *(const float4*)(arow + f0 + (aC4 + 4) * 4);
        uint4 pv = make_uint4(0, 0, 0, 0);
        float sc = 0.f;
        if (bActive) {
            pv = *(const uint4*)(wrow + f0 / 2);
            sc = ldf(Sp, sbf, sBase + kc) * 0.5f;
        }
        __syncthreads();
        {
            int k0 = aC4 * 4, k1 = (aC4 + 4) * 4;
            As[k0 + 0][aRow] = a0.x; As[k0 + 1][aRow] = a0.y;
            As[k0 + 2][aRow] = a0.z; As[k0 + 3][aRow] = a0.w;
            As[k1 + 0][aRow] = a1.x; As[k1 + 1][aRow] = a1.y;
            As[k1 + 2][aRow] = a1.z; As[k1 + 3][aRow] = a1.w;
        }
        if (bActive) {
            unsigned wds[4] = {pv.x, pv.y, pv.z, pv.w};
            #pragma unroll
            for (int b = 0; b < 4; b++) {
                unsigned wd = wds[b];
                #pragma unroll
                for (int j = 0; j < 4; j++) {
                    unsigned byte = (wd >> (8 * j)) & 255u;
                    int k = b * 8 + j * 2;
                    Bs[k + 0][bn] = fp4v(byte & 15u) * sc;
                    Bs[k + 1][bn] = fp4v(byte >> 4)  * sc;
                }
            }
        }
        __syncthreads();
        #pragma unroll
        for (int k = 0; k < 32; k++) {
            float4 av = *(const float4*)&As[k][tm * 4];
            float4 bv = *(const float4*)&Bs[k][tn * 4];
            float aa[4] = {av.x, av.y, av.z, av.w};
            float bb[4] = {bv.x, bv.y, bv.z, bv.w};
            #pragma unroll
            for (int i = 0; i < 4; i++)
                #pragma unroll
                for (int j = 0; j < 4; j++)
                    c[i][j] = fmaf(aa[i], bb[j], c[i][j]);
        }
    }

    #pragma unroll
    for (int i = 0; i < 4; i++) {
        int mi = tm * 4 + i;
        if (m0 + mi < cnt) {
            int slot = sSlot[mi];
            float4 o = make_float4(c[i][0], c[i][1], c[i][2], c[i][3]);
            *(float4*)(g_part + (size_t)slot * H_DIM + n0 + tn * 4) = o;
        }
    }
}

// deterministic 4-way reduce; dtype-flexible output
__global__ void k_reduce(void* __restrict__ outv) {
    int idx = blockIdx.x * 256 + threadIdx.x;
    int t = idx / (H_DIM / 4);
    int c = idx % (H_DIM / 4);
    const float4* p = (const float4*)g_part;
    float4 a = p[(size_t)(t * 4 + 0) * (H_DIM / 4) + c];
    float4 b = p[(size_t)(t * 4 + 1) * (H_DIM / 4) + c];
    float4 d = p[(size_t)(t * 4 + 2) * (H_DIM / 4) + c];
    float4 e = p[(size_t)(t * 4 + 3) * (H_DIM / 4) + c];
    float s0 = a.x + b.x + d.x + e.x, s1 = a.y + b.y + d.y + e.y;
    float s2 = a.z + b.z + d.z + e.z, s3 = a.w + b.w + d.w + e.w;
    if (g_bf[7]) {
        __nv_bfloat16* ob = (__nv_bfloat16*)outv;
        size_t base = (size_t)t * H_DIM + c * 4;
        ob[base + 0] = __float2bfloat16(s0);
        ob[base + 1] = __float2bfloat16(s1);
        ob[base + 2] = __float2bfloat16(s2);
        ob[base + 3] = __float2bfloat16(s3);
    } else {
        ((float4*)outv)[(size_t)t * (H_DIM / 4) + c] = make_float4(s0, s1, s2, s3);
    }
}

extern "C" void kernel_launch(void* const* d_in, const int* in_sizes, int n_in,
                              void* d_out, int out_size) {
    InPtrs in;
    int n = (n_in < 8) ? n_in : 8;
    for (int i = 0; i < 8; i++) {
        in.p[i]  = (i < n) ? d_in[i] : nullptr;
        in.sz[i] = (i < n) ? (long long)in_sizes[i] : 0;
    }
    in.n = n;

    uint8_t* guw = nullptr; cudaGetSymbolAddress((void**)&guw, g_guw);
    uint8_t* dwn = nullptr; cudaGetSymbolAddress((void**)&dwn, g_dwn);

    const size_t GU_BYTES = (size_t)NEXP * 2 * F_DIM * (H_DIM / 2);
    const size_t DW_BYTES = (size_t)NEXP * H_DIM * (F_DIM / 2);

    k_resolve<<<1, 256>>>(in);
    k_repack<<<(unsigned)((GU_BYTES / 4 + 255) / 256), 256>>>(guw, 3, GU_BYTES);
    k_repack<<<(unsigned)((DW_BYTES / 4 + 255) / 256), 256>>>(dwn, 5, DW_BYTES);
    k_route<<<NSLOT / 256, 256>>>();
    k_gemm1<<<dim3(F_DIM / 64, NSLOT / 64, NEXP), 256>>>();
    k_gemm2<<<dim3(H_DIM / 64, NSLOT / 64, NEXP), 256>>>();
    k_reduce<<<(T_TOK * H_DIM / 4) / 256, 256>>>(d_out);
}

// round 12
// speedup vs baseline: 13.1222x; 2.3708x over previous
#include <cuda_runtime.h>
#include <cuda_bf16.h>
#include <mma.h>
#include <cstdint>

using namespace nvcuda;

#define T_TOK 2048
#define H_DIM 2048
#define F_DIM 1024
#define NEXP  16
#define TOPK  4
#define NSLOT (T_TOK * TOPK)   // 8192

// ---------------- device scratch ----------------
__device__ int   g_cnt[NEXP];
__device__ int   g_slot[NEXP * NSLOT];
__device__ float g_wt[NEXP * NSLOT];
__device__ float g_part[(size_t)NSLOT * H_DIM];                    // 64 MB
__device__ __nv_bfloat16 g_wgu[(size_t)NEXP * 2 * F_DIM * H_DIM];  // 128 MB dequant
__device__ __nv_bfloat16 g_wdn[(size_t)NEXP * H_DIM * F_DIM];      // 64 MB dequant
__device__ __nv_bfloat16 g_xhi[(size_t)T_TOK * H_DIM];             // 8 MB
__device__ __nv_bfloat16 g_xlo[(size_t)T_TOK * H_DIM];             // 8 MB
__device__ __nv_bfloat16 g_ahi[(size_t)NSLOT * F_DIM];             // 16 MB
__device__ __nv_bfloat16 g_alo[(size_t)NSLOT * F_DIM];             // 16 MB

// resolved pointers: 0=x 1=ids 2=wts 3=guw 4=gus 5=dwn 6=dsc
__device__ const void* g_rp[7];
__device__ int g_bf[8];

struct InPtrs { const void* p[8]; long long sz[8]; int n; };

__device__ __forceinline__ float bfh(unsigned h) { return __uint_as_float(h << 16); }

// ---------------- content+dtype based input resolution (proven R8) ----------------
__global__ void k_resolve(InPtrs in) {
    __shared__ int cls[8], bff[8];
    __shared__ long long ssz[8];
    int w = threadIdx.x >> 5, lane = threadIdx.x & 31;
    if (w < 8 && lane == 0) { cls[w] = -1; bff[w] = 0; ssz[w] = 0; }
    __syncthreads();
    if (w < in.n && w < 8) {
        const unsigned* u = (const unsigned*)in.p[w];
        bool lt16 = true, i64ids = true, i64b = true, u32b = true;
        bool fint16 = true, fint256 = true;
        bool f32unit = true, f32mant0 = true, f32small = true;
        bool bfunit = true, bfpow2 = true, bfsmall = true;
        bool neg32 = false, pos32 = false, negB = false, posB = false;
        #pragma unroll
        for (int j = 0; j < 4; j++) {
            int idx = lane + 32 * j;
            unsigned v = u[idx];
            lt16   &= (v < 16u);
            i64ids &= (idx & 1) ? (v == 0u) : (v < 16u);
            i64b   &= (idx & 1) ? (v == 0u) : (v < 256u);
            u32b   &= (v < 256u);
            float f = __uint_as_float(v);
            unsigned ex = (v >> 23) & 255u;
            bool fin = (ex != 255u);
            bool isint = fin && f >= 0.f && f == floorf(f);
            fint16  &= (isint && f < 16.f);
            fint256 &= (isint && f < 256.f);
            f32unit  &= (fin && f > 0.f && f < 1.f);
            f32mant0 &= ((v & 0x7FFFFFu) == 0u);
            f32small &= (fin && fabsf(f) < 100.f);
            neg32 |= (f < 0.f); pos32 |= (f > 0.f);
            unsigned hs[2] = { v >> 16, v & 0xFFFFu };
            #pragma unroll
            for (int q = 0; q < 2; q++) {
                unsigned h = hs[q];
                float fb = bfh(h);
                bool finB = (((h >> 7) & 255u) != 255u);
                bfunit  &= (finB && fb > 0.f && fb < 1.f);
                bfpow2  &= (finB && fb > 0.f && fb < 1.f && ((h & 127u) == 0u));
                bfsmall &= (finB && fabsf(fb) < 100.f);
                negB |= (fb < 0.f); posB |= (fb > 0.f);
            }
        }
        unsigned full = ~0u;
        lt16 = __all_sync(full, lt16);       i64ids = __all_sync(full, i64ids);
        i64b = __all_sync(full, i64b);       u32b = __all_sync(full, u32b);
        fint16 = __all_sync(full, fint16);   fint256 = __all_sync(full, fint256);
        f32unit = __all_sync(full, f32unit); f32mant0 = __all_sync(full, f32mant0);
        f32small = __all_sync(full, f32small);
        bfunit = __all_sync(full, bfunit);   bfpow2 = __all_sync(full, bfpow2);
        bfsmall = __all_sync(full, bfsmall);
        neg32 = __any_sync(full, neg32);     pos32 = __any_sync(full, pos32);
        negB = __any_sync(full, negB);       posB = __any_sync(full, posB);
        if (lane == 0) {
            int c, bf = 0;
            if (lt16)                         { c = 0; }
            else if (i64ids)                  { c = 0; bf = 2; }
            else if (fint16)                  { c = 0; bf = 3; }
            else if (i64b)                    { c = 4; bf = 5; }
            else if (u32b)                    { c = 4; bf = 3; }
            else if (fint256)                 { c = 4; bf = 4; }
            else if (f32unit && f32mant0)     { c = 2; }
            else if (bfunit && bfpow2)        { c = 2; bf = 1; }
            else if (f32unit)                 { c = 1; }
            else if (bfunit)                  { c = 1; bf = 1; }
            else if (f32small && neg32 && pos32) { c = 3; }
            else if (bfsmall && negB && posB)    { c = 3; bf = 1; }
            else                              { c = 4; bf = 0; }
            cls[w] = c; bff[w] = bf; ssz[w] = in.sz[w];
        }
    }
    __syncthreads();
    if (threadIdx.x == 0) {
        int ix = -1, ii = -1, iw = -1, s1 = -1, s2 = -1, p1 = -1, p2 = -1;
        for (int i = 0; i < in.n && i < 8; i++) {
            switch (cls[i]) {
                case 0: ii = i; break;
                case 1: iw = i; break;
                case 2: if (s1 < 0) s1 = i; else s2 = i; break;
                case 3: ix = i; break;
                case 4: if (p1 < 0) p1 = i; else p2 = i; break;
                default: break;
            }
        }
        if (ix >= 0 && ii >= 0 && iw >= 0 && s2 >= 0 && p2 >= 0) {
            int gus_i = s1, dsc_i = s2;
            if (ssz[s2] > ssz[s1]) { gus_i = s2; dsc_i = s1; }
            int guw_i = p1, dwn_i = p2;
            if (ssz[p2] > ssz[p1]) { guw_i = p2; dwn_i = p1; }
            g_rp[0] = in.p[ix];    g_bf[0] = bff[ix];
            g_rp[1] = in.p[ii];    g_bf[1] = bff[ii];
            g_rp[2] = in.p[iw];    g_bf[2] = bff[iw];
            g_rp[3] = in.p[guw_i]; g_bf[3] = bff[guw_i];
            g_rp[4] = in.p[gus_i]; g_bf[4] = bff[gus_i];
            g_rp[5] = in.p[dwn_i]; g_bf[5] = bff[dwn_i];
            g_rp[6] = in.p[dsc_i]; g_bf[6] = bff[dsc_i];
            g_bf[7] = bff[ix];
        } else {
            g_rp[0] = in.p[0]; g_rp[2] = in.p[1]; g_rp[1] = in.p[2];
            g_rp[3] = in.p[3]; g_rp[4] = in.p[4]; g_rp[5] = in.p[5]; g_rp[6] = in.p[6];
            for (int i = 0; i < 8; i++) g_bf[i] = 0;
        }
        for (int e = 0; e < NEXP; e++) g_cnt[e] = 0;
    }
}

// ---------------- helpers ----------------
__device__ __forceinline__ float ldf(const void* p, int bf, size_t i) {
    return bf ? __bfloat162float(((const __nv_bfloat16*)p)[i]) : ((const float*)p)[i];
}
__device__ __forceinline__ int ldid(const void* p, int flag, int i) {
    if (flag == 2) return (int)((const long long*)p)[i];
    if (flag == 3) return (int)((const float*)p)[i];
    return ((const int*)p)[i];
}
__device__ __forceinline__ unsigned ldb(const void* p, int m, size_t i) {
    switch (m) {
        case 3:  return ((const unsigned*)p)[i] & 255u;
        case 4:  return (unsigned)((const float*)p)[i] & 255u;
        case 5:  return (unsigned)(((const unsigned long long*)p)[i] & 255ull);
        default: return ((const uint8_t*)p)[i];
    }
}
// e2m1 magnitudes *2 packed as hex digits; caller folds *0.5 into scale
__device__ __forceinline__ float fp4v(unsigned n) {
    float m = (float)((0xC8643210u >> ((n & 7u) * 4)) & 15u);
    return (n & 8u) ? -m : m;
}
__device__ __forceinline__ uint32_t pack_bf2(float a, float b) {
    unsigned short ha = __bfloat16_as_ushort(__float2bfloat16(a));
    unsigned short hb = __bfloat16_as_ushort(__float2bfloat16(b));
    return (uint32_t)ha | ((uint32_t)hb << 16);
}

// ---------------- one-time weight dequant to bf16 ----------------
__global__ void k_deq_gu() {
    size_t i = (size_t)blockIdx.x * 256 + threadIdx.x;
    const void* W = g_rp[3]; const int m = g_bf[3];
    const void* S = g_rp[4]; const int sbf = g_bf[4];
    size_t row = i >> 8;
    unsigned cb = ((unsigned)i & 255u) * 4u;
    float sc = ldf(S, sbf, row * 64 + (cb >> 4)) * 0.5f;
    float v[8];
    #pragma unroll
    for (int q = 0; q < 4; q++) {
        unsigned by = ldb(W, m, row * 1024 + cb + q);
        v[2 * q]     = fp4v(by & 15u) * sc;
        v[2 * q + 1] = fp4v(by >> 4)  * sc;
    }
    uint4 o = make_uint4(pack_bf2(v[0], v[1]), pack_bf2(v[2], v[3]),
                         pack_bf2(v[4], v[5]), pack_bf2(v[6], v[7]));
    ((uint4*)g_wgu)[i] = o;
}
__global__ void k_deq_dn() {
    size_t i = (size_t)blockIdx.x * 256 + threadIdx.x;
    const void* W = g_rp[5]; const int m = g_bf[5];
    const void* S = g_rp[6]; const int sbf = g_bf[6];
    size_t row = i >> 7;
    unsigned cb = ((unsigned)i & 127u) * 4u;
    float sc = ldf(S, sbf, row * 32 + (cb >> 4)) * 0.5f;
    float v[8];
    #pragma unroll
    for (int q = 0; q < 4; q++) {
        unsigned by = ldb(W, m, row * 512 + cb + q);
        v[2 * q]     = fp4v(by & 15u) * sc;
        v[2 * q + 1] = fp4v(by >> 4)  * sc;
    }
    uint4 o = make_uint4(pack_bf2(v[0], v[1]), pack_bf2(v[2], v[3]),
                         pack_bf2(v[4], v[5]), pack_bf2(v[6], v[7]));
    ((uint4*)g_wdn)[i] = o;
}

// ---------------- split x into hi/lo bf16 ----------------
__global__ void k_split_x() {
    size_t g = (size_t)blockIdx.x * 256 + threadIdx.x;
    const void* xp = g_rp[0]; const int xbf = g_bf[0];
    size_t b = g * 4;
    uint32_t hi[2], lo[2];
    #pragma unroll
    for (int q = 0; q < 2; q++) {
        float v0 = ldf(xp, xbf, b + 2 * q);
        float v1 = ldf(xp, xbf, b + 2 * q + 1);
        __nv_bfloat16 h0 = __float2bfloat16(v0), h1 = __float2bfloat16(v1);
        float r0 = v0 - __bfloat162float(h0), r1 = v1 - __bfloat162float(h1);
        hi[q] = (uint32_t)__bfloat16_as_ushort(h0) | ((uint32_t)__bfloat16_as_ushort(h1) << 16);
        lo[q] = (uint32_t)__bfloat16_as_ushort(__float2bfloat16(r0)) |
                ((uint32_t)__bfloat16_as_ushort(__float2bfloat16(r1)) << 16);
    }
    ((uint2*)g_xhi)[g] = make_uint2(hi[0], hi[1]);
    ((uint2*)g_xlo)[g] = make_uint2(lo[0], lo[1]);
}

// ---------------- routing ----------------
__global__ void k_route() {
    int s = blockIdx.x * 256 + threadIdx.x;
    if (s >= NSLOT) return;
    int e = ldid(g_rp[1], g_bf[1], s) & (NEXP - 1);
    int p = atomicAdd(&g_cnt[e], 1);
    g_slot[e * NSLOT + p] = s;
    g_wt[e * NSLOT + p]   = ldf(g_rp[2], g_bf[2], s);
}

// =====================================================================
// wmma bf16 grouped GEMMs. CTA tile M=128 x N=128, BK=64, 8 warps (4x2).
// hi/lo A passes accumulate into the same fp32 accumulator.
// =====================================================================
extern __shared__ char dsm[];
#define LDA 72      // smem leading dim (bf16 elements)
#define LDS_ 132    // epilogue float leading dim

// GEMM1: per (64-f tile, 128-slot tile, expert): gate|up, fused SwiGLU
__global__ void __launch_bounds__(256) k_mma1() {
    const int e = blockIdx.z, cnt = g_cnt[e];
    const int m0 = blockIdx.y * 128;
    if (m0 >= cnt) return;
    const int n0 = blockIdx.x * 64;

    __nv_bfloat16* sAhi = (__nv_bfloat16*)dsm;
    __nv_bfloat16* sAlo = (__nv_bfloat16*)(dsm + 18432);
    __nv_bfloat16* sB   = (__nv_bfloat16*)(dsm + 36864);
    float* S = (float*)dsm;

    __shared__ int sSlot[128], sTok[128];
    __shared__ float sWt[128];

    const int tid = threadIdx.x, wid = tid >> 5;
    if (tid < 128) {
        int m = m0 + tid;
        int sl = (m < cnt) ? g_slot[e * NSLOT + m] : g_slot[e * NSLOT];
        sSlot[tid] = sl; sTok[tid] = sl >> 2;
        sWt[tid] = (m < cnt) ? g_wt[e * NSLOT + m] : 0.f;
    }
    __syncthreads();

    const int wm = (wid & 3) * 32, wn = (wid >> 2) * 64;
    wmma::fragment<wmma::accumulator, 16, 16, 16, float> acc[2][4];
    #pragma unroll
    for (int i = 0; i < 2; i++)
        #pragma unroll
        for (int j = 0; j < 4; j++) wmma::fill_fragment(acc[i][j], 0.f);

    const __nv_bfloat16* BGU = g_wgu + (size_t)e * 2 * F_DIM * H_DIM;

    for (int kc = 0; kc < H_DIM / 64; kc++) {
        __syncthreads();
        #pragma unroll
        for (int q = 0; q < 4; q++) {
            int i = tid + q * 256;
            int r = i >> 3, c8 = i & 7;
            size_t src = (size_t)sTok[r] * H_DIM + kc * 64 + c8 * 8;
            *(uint4*)(sAhi + r * LDA + c8 * 8) = *(const uint4*)(g_xhi + src);
            *(uint4*)(sAlo + r * LDA + c8 * 8) = *(const uint4*)(g_xlo + src);
            int rowW = (r < 64) ? (n0 + r) : (F_DIM + n0 + r - 64);
            size_t ws = (size_t)rowW * H_DIM + kc * 64 + c8 * 8;
            *(uint4*)(sB + r * LDA + c8 * 8) = *(const uint4*)(BGU + ws);
        }
        __syncthreads();
        #pragma unroll
        for (int ks = 0; ks < 4; ks++) {
            wmma::fragment<wmma::matrix_b, 16, 16, 16, __nv_bfloat16, wmma::col_major> bf[4];
            #pragma unroll
            for (int nf = 0; nf < 4; nf++)
                wmma::load_matrix_sync(bf[nf], sB + (wn + nf * 16) * LDA + ks * 16, LDA);
            #pragma unroll
            for (int mf = 0; mf < 2; mf++) {
                wmma::fragment<wmma::matrix_a, 16, 16, 16, __nv_bfloat16, wmma::row_major> ah, al;
                wmma::load_matrix_sync(ah, sAhi + (wm + mf * 16) * LDA + ks * 16, LDA);
                wmma::load_matrix_sync(al, sAlo + (wm + mf * 16) * LDA + ks * 16, LDA);
                #pragma unroll
                for (int nf = 0; nf < 4; nf++) {
                    wmma::mma_sync(acc[mf][nf], ah, bf[nf], acc[mf][nf]);
                    wmma::mma_sync(acc[mf][nf], al, bf[nf], acc[mf][nf]);
                }
            }
        }
    }
    __syncthreads();
    #pragma unroll
    for (int mf = 0; mf < 2; mf++)
        #pragma unroll
        for (int nf = 0; nf < 4; nf++)
            wmma::store_matrix_sync(S + (wm + mf * 16) * LDS_ + wn + nf * 16,
                                    acc[mf][nf], LDS_, wmma::mem_row_major);
    __syncthreads();

    // SwiGLU epilogue: cols [0,64)=gate, [64,128)=up → act hi/lo
    {
        const int row = tid >> 1, j0 = (tid & 1) * 32;
        if (m0 + row < cnt) {
            const float wt = sWt[row];
            const size_t arow = (size_t)sSlot[row] * F_DIM + n0 + j0;
            #pragma unroll
            for (int q = 0; q < 4; q++) {
                uint32_t hw[4], lw[4];
                #pragma unroll
                for (int r2 = 0; r2 < 4; r2++) {
                    int j = j0 + q * 8 + r2 * 2;
                    float g0 = S[row * LDS_ + j],     u0 = S[row * LDS_ + 64 + j];
                    float g1 = S[row * LDS_ + j + 1], u1 = S[row * LDS_ + 65 + j];
                    float v0 = g0 * (1.f / (1.f + __expf(-g0))) * u0 * wt;
                    float v1 = g1 * (1.f / (1.f + __expf(-g1))) * u1 * wt;
                    __nv_bfloat16 h0 = __float2bfloat16(v0), h1 = __float2bfloat16(v1);
                    float r0 = v0 - __bfloat162float(h0), r1 = v1 - __bfloat162float(h1);
                    hw[r2] = (uint32_t)__bfloat16_as_ushort(h0) | ((uint32_t)__bfloat16_as_ushort(h1) << 16);
                    lw[r2] = (uint32_t)__bfloat16_as_ushort(__float2bfloat16(r0)) |
                             ((uint32_t)__bfloat16_as_ushort(__float2bfloat16(r1)) << 16);
                }
                ((uint4*)(g_ahi + arow))[q] = make_uint4(hw[0], hw[1], hw[2], hw[3]);
                ((uint4*)(g_alo + arow))[q] = make_uint4(lw[0], lw[1], lw[2], lw[3]);
            }
        }
    }
}

// GEMM2: per (128-h tile, 128-slot tile, expert): part = act @ Wd^T
__global__ void __launch_bounds__(256) k_mma2() {
    const int e = blockIdx.z, cnt = g_cnt[e];
    const int m0 = blockIdx.y * 128;
    if (m0 >= cnt) return;
    const int n0 = blockIdx.x * 128;

    __nv_bfloat16* sAhi = (__nv_bfloat16*)dsm;
    __nv_bfloat16* sAlo = (__nv_bfloat16*)(dsm + 18432);
    __nv_bfloat16* sB   = (__nv_bfloat16*)(dsm + 36864);
    float* S = (float*)dsm;

    __shared__ int sSlot[128];

    const int tid = threadIdx.x, wid = tid >> 5;
    if (tid < 128) {
        int m = m0 + tid;
        sSlot[tid] = (m < cnt) ? g_slot[e * NSLOT + m] : g_slot[e * NSLOT];
    }
    __syncthreads();

    const int wm = (wid & 3) * 32, wn = (wid >> 2) * 64;
    wmma::fragment<wmma::accumulator, 16, 16, 16, float> acc[2][4];
    #pragma unroll
    for (int i = 0; i < 2; i++)
        #pragma unroll
        for (int j = 0; j < 4; j++) wmma::fill_fragment(acc[i][j], 0.f);

    const __nv_bfloat16* BW = g_wdn + (size_t)e * H_DIM * F_DIM;

    for (int kc = 0; kc < F_DIM / 64; kc++) {
        __syncthreads();
        #pragma unroll
        for (int q = 0; q < 4; q++) {
            int i = tid + q * 256;
            int r = i >> 3, c8 = i & 7;
            size_t src = (size_t)sSlot[r] * F_DIM + kc * 64 + c8 * 8;
            *(uint4*)(sAhi + r * LDA + c8 * 8) = *(const uint4*)(g_ahi + src);
            *(uint4*)(sAlo + r * LDA + c8 * 8) = *(const uint4*)(g_alo + src);
            size_t ws = (size_t)(n0 + r) * F_DIM + kc * 64 + c8 * 8;
            *(uint4*)(sB + r * LDA + c8 * 8) = *(const uint4*)(BW + ws);
        }
        __syncthreads();
        #pragma unroll
        for (int ks = 0; ks < 4; ks++) {
            wmma::fragment<wmma::matrix_b, 16, 16, 16, __nv_bfloat16, wmma::col_major> bf[4];
            #pragma unroll
            for (int nf = 0; nf < 4; nf++)
                wmma::load_matrix_sync(bf[nf], sB + (wn + nf * 16) * LDA + ks * 16, LDA);
            #pragma unroll
            for (int mf = 0; mf < 2; mf++) {
                wmma::fragment<wmma::matrix_a, 16, 16, 16, __nv_bfloat16, wmma::row_major> ah, al;
                wmma::load_matrix_sync(ah, sAhi + (wm + mf * 16) * LDA + ks * 16, LDA);
                wmma::load_matrix_sync(al, sAlo + (wm + mf * 16) * LDA + ks * 16, LDA);
                #pragma unroll
                for (int nf = 0; nf < 4; nf++) {
                    wmma::mma_sync(acc[mf][nf], ah, bf[nf], acc[mf][nf]);
                    wmma::mma_sync(acc[mf][nf], al, bf[nf], acc[mf][nf]);
                }
            }
        }
    }
    __syncthreads();
    #pragma unroll
    for (int mf = 0; mf < 2; mf++)
        #pragma unroll
        for (int nf = 0; nf < 4; nf++)
            wmma::store_matrix_sync(S + (wm + mf * 16) * LDS_ + wn + nf * 16,
                                    acc[mf][nf], LDS_, wmma::mem_row_major);
    __syncthreads();

    {
        const int row = tid >> 1, h0 = (tid & 1) * 64;
        if (m0 + row < cnt) {
            const size_t prow = (size_t)sSlot[row] * H_DIM + n0 + h0;
            #pragma unroll
            for (int q = 0; q < 16; q++) {
                float4 o = make_float4(S[row * LDS_ + h0 + q * 4],
                                       S[row * LDS_ + h0 + q * 4 + 1],
                                       S[row * LDS_ + h0 + q * 4 + 2],
                                       S[row * LDS_ + h0 + q * 4 + 3]);
                ((float4*)(g_part + prow))[q] = o;
            }
        }
    }
}

// deterministic 4-way reduce; dtype-flexible output
__global__ void k_reduce(void* __restrict__ outv) {
    int idx = blockIdx.x * 256 + threadIdx.x;
    int t = idx / (H_DIM / 4);
    int c = idx % (H_DIM / 4);
    const float4* p = (const float4*)g_part;
    float4 a = p[(size_t)(t * 4 + 0) * (H_DIM / 4) + c];
    float4 b = p[(size_t)(t * 4 + 1) * (H_DIM / 4) + c];
    float4 d = p[(size_t)(t * 4 + 2) * (H_DIM / 4) + c];
    float4 e = p[(size_t)(t * 4 + 3) * (H_DIM / 4) + c];
    float s0 = a.x + b.x + d.x + e.x, s1 = a.y + b.y + d.y + e.y;
    float s2 = a.z + b.z + d.z + e.z, s3 = a.w + b.w + d.w + e.w;
    if (g_bf[7]) {
        __nv_bfloat16* ob = (__nv_bfloat16*)outv;
        size_t base = (size_t)t * H_DIM + c * 4;
        ob[base + 0] = __float2bfloat16(s0);
        ob[base + 1] = __float2bfloat16(s1);
        ob[base + 2] = __float2bfloat16(s2);
        ob[base + 3] = __float2bfloat16(s3);
    } else {
        ((float4*)outv)[(size_t)t * (H_DIM / 4) + c] = make_float4(s0, s1, s2, s3);
    }
}

extern "C" void kernel_launch(void* const* d_in, const int* in_sizes, int n_in,
                              void* d_out, int out_size) {
    InPtrs in;
    int n = (n_in < 8) ? n_in : 8;
    for (int i = 0; i < 8; i++) {
        in.p[i]  = (i < n) ? d_in[i] : nullptr;
        in.sz[i] = (i < n) ? (long long)in_sizes[i] : 0;
    }
    in.n = n;

    const int DSMEM = 128 * LDS_ * 4;   // 67584 (covers 55296 tile buffers too)
    cudaFuncSetAttribute(k_mma1, cudaFuncAttributeMaxDynamicSharedMemorySize, DSMEM);
    cudaFuncSetAttribute(k_mma2, cudaFuncAttributeMaxDynamicSharedMemorySize, DSMEM);

    k_resolve<<<1, 256>>>(in);
    k_deq_gu<<<(NEXP * 2 * F_DIM * (H_DIM / 2) / 4) / 256, 256>>>();
    k_deq_dn<<<(NEXP * H_DIM * (F_DIM / 2) / 4) / 256, 256>>>();
    k_split_x<<<(T_TOK * H_DIM / 4) / 256, 256>>>();
    k_route<<<NSLOT / 256, 256>>>();
    k_mma1<<<dim3(F_DIM / 64, NSLOT / 128, NEXP), 256, DSMEM>>>();
    k_mma2<<<dim3(H_DIM / 128, NSLOT / 128, NEXP), 256, DSMEM>>>();
    k_reduce<<<(T_TOK * H_DIM / 4) / 256, 256>>>(d_out);
}

// round 13
// speedup vs baseline: 20.6090x; 1.5705x over previous
#include <cuda_runtime.h>
#include <cuda_bf16.h>
#include <mma.h>
#include <cstdint>

using namespace nvcuda;

#define T_TOK 2048
#define H_DIM 2048
#define F_DIM 1024
#define NEXP  16
#define TOPK  4
#define NSLOT (T_TOK * TOPK)   // 8192

// ---------------- device scratch ----------------
__device__ int   g_cnt[NEXP];
__device__ int   g_slot[NEXP * NSLOT];
__device__ float g_wt[NEXP * NSLOT];
__device__ float g_part[(size_t)NSLOT * H_DIM];                    // 64 MB
__device__ __nv_bfloat16 g_wgu[(size_t)NEXP * 2 * F_DIM * H_DIM];  // 128 MB dequant
__device__ __nv_bfloat16 g_wdn[(size_t)NEXP * H_DIM * F_DIM];      // 64 MB dequant
__device__ __nv_bfloat16 g_xhi[(size_t)T_TOK * H_DIM];             // 8 MB
__device__ __nv_bfloat16 g_xlo[(size_t)T_TOK * H_DIM];             // 8 MB
__device__ __nv_bfloat16 g_ahi[(size_t)NSLOT * F_DIM];             // 16 MB
__device__ __nv_bfloat16 g_alo[(size_t)NSLOT * F_DIM];             // 16 MB

// resolved pointers: 0=x 1=ids 2=wts 3=guw 4=gus 5=dwn 6=dsc
__device__ const void* g_rp[7];
__device__ int g_bf[8];

struct InPtrs { const void* p[8]; long long sz[8]; int n; };

__device__ __forceinline__ float bfh(unsigned h) { return __uint_as_float(h << 16); }

// ---------------- content+dtype based input resolution (proven R8) ----------------
__global__ void k_resolve(InPtrs in) {
    __shared__ int cls[8], bff[8];
    __shared__ long long ssz[8];
    int w = threadIdx.x >> 5, lane = threadIdx.x & 31;
    if (w < 8 && lane == 0) { cls[w] = -1; bff[w] = 0; ssz[w] = 0; }
    __syncthreads();
    if (w < in.n && w < 8) {
        const unsigned* u = (const unsigned*)in.p[w];
        bool lt16 = true, i64ids = true, i64b = true, u32b = true;
        bool fint16 = true, fint256 = true;
        bool f32unit = true, f32mant0 = true, f32small = true;
        bool bfunit = true, bfpow2 = true, bfsmall = true;
        bool neg32 = false, pos32 = false, negB = false, posB = false;
        #pragma unroll
        for (int j = 0; j < 4; j++) {
            int idx = lane + 32 * j;
            unsigned v = u[idx];
            lt16   &= (v < 16u);
            i64ids &= (idx & 1) ? (v == 0u) : (v < 16u);
            i64b   &= (idx & 1) ? (v == 0u) : (v < 256u);
            u32b   &= (v < 256u);
            float f = __uint_as_float(v);
            unsigned ex = (v >> 23) & 255u;
            bool fin = (ex != 255u);
            bool isint = fin && f >= 0.f && f == floorf(f);
            fint16  &= (isint && f < 16.f);
            fint256 &= (isint && f < 256.f);
            f32unit  &= (fin && f > 0.f && f < 1.f);
            f32mant0 &= ((v & 0x7FFFFFu) == 0u);
            f32small &= (fin && fabsf(f) < 100.f);
            neg32 |= (f < 0.f); pos32 |= (f > 0.f);
            unsigned hs[2] = { v >> 16, v & 0xFFFFu };
            #pragma unroll
            for (int q = 0; q < 2; q++) {
                unsigned h = hs[q];
                float fb = bfh(h);
                bool finB = (((h >> 7) & 255u) != 255u);
                bfunit  &= (finB && fb > 0.f && fb < 1.f);
                bfpow2  &= (finB && fb > 0.f && fb < 1.f && ((h & 127u) == 0u));
                bfsmall &= (finB && fabsf(fb) < 100.f);
                negB |= (fb < 0.f); posB |= (fb > 0.f);
            }
        }
        unsigned full = ~0u;
        lt16 = __all_sync(full, lt16);       i64ids = __all_sync(full, i64ids);
        i64b = __all_sync(full, i64b);       u32b = __all_sync(full, u32b);
        fint16 = __all_sync(full, fint16);   fint256 = __all_sync(full, fint256);
        f32unit = __all_sync(full, f32unit); f32mant0 = __all_sync(full, f32mant0);
        f32small = __all_sync(full, f32small);
        bfunit = __all_sync(full, bfunit);   bfpow2 = __all_sync(full, bfpow2);
        bfsmall = __all_sync(full, bfsmall);
        neg32 = __any_sync(full, neg32);     pos32 = __any_sync(full, pos32);
        negB = __any_sync(full, negB);       posB = __any_sync(full, posB);
        if (lane == 0) {
            int c, bf = 0;
            if (lt16)                         { c = 0; }
            else if (i64ids)                  { c = 0; bf = 2; }
            else if (fint16)                  { c = 0; bf = 3; }
            else if (i64b)                    { c = 4; bf = 5; }
            else if (u32b)                    { c = 4; bf = 3; }
            else if (fint256)                 { c = 4; bf = 4; }
            else if (f32unit && f32mant0)     { c = 2; }
            else if (bfunit && bfpow2)        { c = 2; bf = 1; }
            else if (f32unit)                 { c = 1; }
            else if (bfunit)                  { c = 1; bf = 1; }
            else if (f32small && neg32 && pos32) { c = 3; }
            else if (bfsmall && negB && posB)    { c = 3; bf = 1; }
            else                              { c = 4; bf = 0; }
            cls[w] = c; bff[w] = bf; ssz[w] = in.sz[w];
        }
    }
    __syncthreads();
    if (threadIdx.x == 0) {
        int ix = -1, ii = -1, iw = -1, s1 = -1, s2 = -1, p1 = -1, p2 = -1;
        for (int i = 0; i < in.n && i < 8; i++) {
            switch (cls[i]) {
                case 0: ii = i; break;
                case 1: iw = i; break;
                case 2: if (s1 < 0) s1 = i; else s2 = i; break;
                case 3: ix = i; break;
                case 4: if (p1 < 0) p1 = i; else p2 = i; break;
                default: break;
            }
        }
        if (ix >= 0 && ii >= 0 && iw >= 0 && s2 >= 0 && p2 >= 0) {
            int gus_i = s1, dsc_i = s2;
            if (ssz[s2] > ssz[s1]) { gus_i = s2; dsc_i = s1; }
            int guw_i = p1, dwn_i = p2;
            if (ssz[p2] > ssz[p1]) { guw_i = p2; dwn_i = p1; }
            g_rp[0] = in.p[ix];    g_bf[0] = bff[ix];
            g_rp[1] = in.p[ii];    g_bf[1] = bff[ii];
            g_rp[2] = in.p[iw];    g_bf[2] = bff[iw];
            g_rp[3] = in.p[guw_i]; g_bf[3] = bff[guw_i];
            g_rp[4] = in.p[gus_i]; g_bf[4] = bff[gus_i];
            g_rp[5] = in.p[dwn_i]; g_bf[5] = bff[dwn_i];
            g_rp[6] = in.p[dsc_i]; g_bf[6] = bff[dsc_i];
            g_bf[7] = bff[ix];
        } else {
            g_rp[0] = in.p[0]; g_rp[2] = in.p[1]; g_rp[1] = in.p[2];
            g_rp[3] = in.p[3]; g_rp[4] = in.p[4]; g_rp[5] = in.p[5]; g_rp[6] = in.p[6];
            for (int i = 0; i < 8; i++) g_bf[i] = 0;
        }
        for (int e = 0; e < NEXP; e++) g_cnt[e] = 0;
    }
}

// ---------------- helpers ----------------
__device__ __forceinline__ float ldf(const void* p, int bf, size_t i) {
    return bf ? __bfloat162float(((const __nv_bfloat16*)p)[i]) : ((const float*)p)[i];
}
__device__ __forceinline__ int ldid(const void* p, int flag, int i) {
    if (flag == 2) return (int)((const long long*)p)[i];
    if (flag == 3) return (int)((const float*)p)[i];
    return ((const int*)p)[i];
}
__device__ __forceinline__ unsigned ldb(const void* p, int m, size_t i) {
    switch (m) {
        case 3:  return ((const unsigned*)p)[i] & 255u;
        case 4:  return (unsigned)((const float*)p)[i] & 255u;
        case 5:  return (unsigned)(((const unsigned long long*)p)[i] & 255ull);
        default: return ((const uint8_t*)p)[i];
    }
}
__device__ __forceinline__ float fp4v(unsigned n) {
    float m = (float)((0xC8643210u >> ((n & 7u) * 4)) & 15u);
    return (n & 8u) ? -m : m;
}
__device__ __forceinline__ uint32_t pack_bf2(float a, float b) {
    unsigned short ha = __bfloat16_as_ushort(__float2bfloat16(a));
    unsigned short hb = __bfloat16_as_ushort(__float2bfloat16(b));
    return (uint32_t)ha | ((uint32_t)hb << 16);
}
__device__ __forceinline__ uint32_t s2u(const void* p) {
    uint32_t a;
    asm("{ .reg .u64 t; cvta.to.shared.u64 t, %1; cvt.u32.u64 %0, t; }" : "=r"(a) : "l"(p));
    return a;
}
__device__ __forceinline__ void cp16(uint32_t saddr, const void* gaddr) {
    asm volatile("cp.async.cg.shared.global [%0], [%1], 16;" :: "r"(saddr), "l"(gaddr) : "memory");
}
__device__ __forceinline__ void cp_commit() {
    asm volatile("cp.async.commit_group;" ::: "memory");
}
template <int N>
__device__ __forceinline__ void cp_wait() {
    asm volatile("cp.async.wait_group %0;" :: "n"(N) : "memory");
}

// ---------------- one-time weight dequant to bf16 ----------------
__global__ void k_deq_gu() {
    size_t i = (size_t)blockIdx.x * 256 + threadIdx.x;
    const void* W = g_rp[3]; const int m = g_bf[3];
    const void* S = g_rp[4]; const int sbf = g_bf[4];
    size_t row = i >> 8;
    unsigned cb = ((unsigned)i & 255u) * 4u;
    float sc = ldf(S, sbf, row * 64 + (cb >> 4)) * 0.5f;
    float v[8];
    #pragma unroll
    for (int q = 0; q < 4; q++) {
        unsigned by = ldb(W, m, row * 1024 + cb + q);
        v[2 * q]     = fp4v(by & 15u) * sc;
        v[2 * q + 1] = fp4v(by >> 4)  * sc;
    }
    uint4 o = make_uint4(pack_bf2(v[0], v[1]), pack_bf2(v[2], v[3]),
                         pack_bf2(v[4], v[5]), pack_bf2(v[6], v[7]));
    ((uint4*)g_wgu)[i] = o;
}
__global__ void k_deq_dn() {
    size_t i = (size_t)blockIdx.x * 256 + threadIdx.x;
    const void* W = g_rp[5]; const int m = g_bf[5];
    const void* S = g_rp[6]; const int sbf = g_bf[6];
    size_t row = i >> 7;
    unsigned cb = ((unsigned)i & 127u) * 4u;
    float sc = ldf(S, sbf, row * 32 + (cb >> 4)) * 0.5f;
    float v[8];
    #pragma unroll
    for (int q = 0; q < 4; q++) {
        unsigned by = ldb(W, m, row * 512 + cb + q);
        v[2 * q]     = fp4v(by & 15u) * sc;
        v[2 * q + 1] = fp4v(by >> 4)  * sc;
    }
    uint4 o = make_uint4(pack_bf2(v[0], v[1]), pack_bf2(v[2], v[3]),
                         pack_bf2(v[4], v[5]), pack_bf2(v[6], v[7]));
    ((uint4*)g_wdn)[i] = o;
}

// ---------------- split x into hi/lo bf16 ----------------
__global__ void k_split_x() {
    size_t g = (size_t)blockIdx.x * 256 + threadIdx.x;
    const void* xp = g_rp[0]; const int xbf = g_bf[0];
    size_t b = g * 4;
    uint32_t hi[2], lo[2];
    #pragma unroll
    for (int q = 0; q < 2; q++) {
        float v0 = ldf(xp, xbf, b + 2 * q);
        float v1 = ldf(xp, xbf, b + 2 * q + 1);
        __nv_bfloat16 h0 = __float2bfloat16(v0), h1 = __float2bfloat16(v1);
        float r0 = v0 - __bfloat162float(h0), r1 = v1 - __bfloat162float(h1);
        hi[q] = (uint32_t)__bfloat16_as_ushort(h0) | ((uint32_t)__bfloat16_as_ushort(h1) << 16);
        lo[q] = (uint32_t)__bfloat16_as_ushort(__float2bfloat16(r0)) |
                ((uint32_t)__bfloat16_as_ushort(__float2bfloat16(r1)) << 16);
    }
    ((uint2*)g_xhi)[g] = make_uint2(hi[0], hi[1]);
    ((uint2*)g_xlo)[g] = make_uint2(lo[0], lo[1]);
}

// ---------------- routing ----------------
__global__ void k_route() {
    int s = blockIdx.x * 256 + threadIdx.x;
    if (s >= NSLOT) return;
    int e = ldid(g_rp[1], g_bf[1], s) & (NEXP - 1);
    int p = atomicAdd(&g_cnt[e], 1);
    g_slot[e * NSLOT + p] = s;
    g_wt[e * NSLOT + p]   = ldf(g_rp[2], g_bf[2], s);
}

// =====================================================================
// wmma bf16 grouped GEMMs, 2-stage cp.async pipeline.
// CTA tile 128x128, BK=64, 8 warps (4x2). hi/lo A accumulate together.
// Stage: sAhi|sAlo|sB, each 128x72 bf16 => 55296 B. Two stages.
// =====================================================================
extern __shared__ char dsm[];
#define LDA 72
#define LDS_ 132
#define STAGE_B 55296

// GEMM1: per (64-f tile, 128-slot tile, expert): gate|up, fused SwiGLU
__global__ void __launch_bounds__(256) k_mma1() {
    const int e = blockIdx.z, cnt = g_cnt[e];
    const int m0 = blockIdx.y * 128;
    if (m0 >= cnt) return;
    const int n0 = blockIdx.x * 64;

    float* S = (float*)dsm;
    __shared__ int sSlot[128], sTok[128];
    __shared__ float sWt[128];

    const int tid = threadIdx.x, wid = tid >> 5;
    if (tid < 128) {
        int m = m0 + tid;
        int sl = (m < cnt) ? g_slot[e * NSLOT + m] : g_slot[e * NSLOT];
        sSlot[tid] = sl; sTok[tid] = sl >> 2;
        sWt[tid] = (m < cnt) ? g_wt[e * NSLOT + m] : 0.f;
    }
    __syncthreads();

    // per-thread copy descriptors (4 chunks of 3x16B per stage)
    const uint32_t smBase = s2u(dsm);
    const __nv_bfloat16* BGU = g_wgu + (size_t)e * 2 * F_DIM * H_DIM;
    const __nv_bfloat16* gHi[4];
    const __nv_bfloat16* gLo[4];
    const __nv_bfloat16* gB[4];
    uint32_t sOff[4];
    #pragma unroll
    for (int q = 0; q < 4; q++) {
        int i = tid + q * 256;
        int r = i >> 3, c8 = i & 7;
        gHi[q] = g_xhi + (size_t)sTok[r] * H_DIM + c8 * 8;
        gLo[q] = g_xlo + (size_t)sTok[r] * H_DIM + c8 * 8;
        int rowW = (r < 64) ? (n0 + r) : (F_DIM + n0 + r - 64);
        gB[q]  = BGU + (size_t)rowW * H_DIM + c8 * 8;
        sOff[q] = (uint32_t)(r * LDA + c8 * 8) * 2u;
    }

    #define ISSUE1(kc) do { \
        uint32_t sb = smBase + (uint32_t)((kc) & 1) * STAGE_B; \
        int koff = (kc) * 64; \
        _Pragma("unroll") \
        for (int q = 0; q < 4; q++) { \
            cp16(sb + sOff[q],          gHi[q] + koff); \
            cp16(sb + 18432 + sOff[q],  gLo[q] + koff); \
            cp16(sb + 36864 + sOff[q],  gB[q]  + koff); \
        } \
        cp_commit(); \
    } while (0)

    const int wm = (wid & 3) * 32, wn = (wid >> 2) * 64;
    wmma::fragment<wmma::accumulator, 16, 16, 16, float> acc[2][4];
    #pragma unroll
    for (int i = 0; i < 2; i++)
        #pragma unroll
        for (int j = 0; j < 4; j++) wmma::fill_fragment(acc[i][j], 0.f);

    const int NK = H_DIM / 64;
    ISSUE1(0);
    for (int kc = 0; kc < NK; kc++) {
        if (kc + 1 < NK) { ISSUE1(kc + 1); cp_wait<1>(); }
        else             { cp_wait<0>(); }
        __syncthreads();
        const char* stg = dsm + (size_t)(kc & 1) * STAGE_B;
        const __nv_bfloat16* sAhi = (const __nv_bfloat16*)stg;
        const __nv_bfloat16* sAlo = (const __nv_bfloat16*)(stg + 18432);
        const __nv_bfloat16* sB   = (const __nv_bfloat16*)(stg + 36864);
        #pragma unroll
        for (int ks = 0; ks < 4; ks++) {
            wmma::fragment<wmma::matrix_b, 16, 16, 16, __nv_bfloat16, wmma::col_major> bf[4];
            #pragma unroll
            for (int nf = 0; nf < 4; nf++)
                wmma::load_matrix_sync(bf[nf], sB + (wn + nf * 16) * LDA + ks * 16, LDA);
            #pragma unroll
            for (int mf = 0; mf < 2; mf++) {
                wmma::fragment<wmma::matrix_a, 16, 16, 16, __nv_bfloat16, wmma::row_major> ah, al;
                wmma::load_matrix_sync(ah, sAhi + (wm + mf * 16) * LDA + ks * 16, LDA);
                wmma::load_matrix_sync(al, sAlo + (wm + mf * 16) * LDA + ks * 16, LDA);
                #pragma unroll
                for (int nf = 0; nf < 4; nf++) {
                    wmma::mma_sync(acc[mf][nf], ah, bf[nf], acc[mf][nf]);
                    wmma::mma_sync(acc[mf][nf], al, bf[nf], acc[mf][nf]);
                }
            }
        }
        __syncthreads();
    }
    #pragma unroll
    for (int mf = 0; mf < 2; mf++)
        #pragma unroll
        for (int nf = 0; nf < 4; nf++)
            wmma::store_matrix_sync(S + (wm + mf * 16) * LDS_ + wn + nf * 16,
                                    acc[mf][nf], LDS_, wmma::mem_row_major);
    __syncthreads();

    // SwiGLU epilogue: cols [0,64)=gate, [64,128)=up → act hi/lo
    {
        const int row = tid >> 1, j0 = (tid & 1) * 32;
        if (m0 + row < cnt) {
            const float wt = sWt[row];
            const size_t arow = (size_t)sSlot[row] * F_DIM + n0 + j0;
            #pragma unroll
            for (int q = 0; q < 4; q++) {
                uint32_t hw[4], lw[4];
                #pragma unroll
                for (int r2 = 0; r2 < 4; r2++) {
                    int j = j0 + q * 8 + r2 * 2;
                    float g0 = S[row * LDS_ + j],     u0 = S[row * LDS_ + 64 + j];
                    float g1 = S[row * LDS_ + j + 1], u1 = S[row * LDS_ + 65 + j];
                    float v0 = g0 * (1.f / (1.f + __expf(-g0))) * u0 * wt;
                    float v1 = g1 * (1.f / (1.f + __expf(-g1))) * u1 * wt;
                    __nv_bfloat16 h0 = __float2bfloat16(v0), h1 = __float2bfloat16(v1);
                    float r0 = v0 - __bfloat162float(h0), r1 = v1 - __bfloat162float(h1);
                    hw[r2] = (uint32_t)__bfloat16_as_ushort(h0) | ((uint32_t)__bfloat16_as_ushort(h1) << 16);
                    lw[r2] = (uint32_t)__bfloat16_as_ushort(__float2bfloat16(r0)) |
                             ((uint32_t)__bfloat16_as_ushort(__float2bfloat16(r1)) << 16);
                }
                ((uint4*)(g_ahi + arow))[q] = make_uint4(hw[0], hw[1], hw[2], hw[3]);
                ((uint4*)(g_alo + arow))[q] = make_uint4(lw[0], lw[1], lw[2], lw[3]);
            }
        }
    }
}

// GEMM2: per (128-h tile, 128-slot tile, expert): part = act @ Wd^T
__global__ void __launch_bounds__(256) k_mma2() {
    const int e = blockIdx.z, cnt = g_cnt[e];
    const int m0 = blockIdx.y * 128;
    if (m0 >= cnt) return;
    const int n0 = blockIdx.x * 128;

    float* S = (float*)dsm;
    __shared__ int sSlot[128];

    const int tid = threadIdx.x, wid = tid >> 5;
    if (tid < 128) {
        int m = m0 + tid;
        sSlot[tid] = (m < cnt) ? g_slot[e * NSLOT + m] : g_slot[e * NSLOT];
    }
    __syncthreads();

    const uint32_t smBase = s2u(dsm);
    const __nv_bfloat16* BW = g_wdn + (size_t)e * H_DIM * F_DIM;
    const __nv_bfloat16* gHi[4];
    const __nv_bfloat16* gLo[4];
    const __nv_bfloat16* gB[4];
    uint32_t sOff[4];
    #pragma unroll
    for (int q = 0; q < 4; q++) {
        int i = tid + q * 256;
        int r = i >> 3, c8 = i & 7;
        gHi[q] = g_ahi + (size_t)sSlot[r] * F_DIM + c8 * 8;
        gLo[q] = g_alo + (size_t)sSlot[r] * F_DIM + c8 * 8;
        gB[q]  = BW + (size_t)(n0 + r) * F_DIM + c8 * 8;
        sOff[q] = (uint32_t)(r * LDA + c8 * 8) * 2u;
    }

    #define ISSUE2(kc) do { \
        uint32_t sb = smBase + (uint32_t)((kc) & 1) * STAGE_B; \
        int koff = (kc) * 64; \
        _Pragma("unroll") \
        for (int q = 0; q < 4; q++) { \
            cp16(sb + sOff[q],          gHi[q] + koff); \
            cp16(sb + 18432 + sOff[q],  gLo[q] + koff); \
            cp16(sb + 36864 + sOff[q],  gB[q]  + koff); \
        } \
        cp_commit(); \
    } while (0)

    const int wm = (wid & 3) * 32, wn = (wid >> 2) * 64;
    wmma::fragment<wmma::accumulator, 16, 16, 16, float> acc[2][4];
    #pragma unroll
    for (int i = 0; i < 2; i++)
        #pragma unroll
        for (int j = 0; j < 4; j++) wmma::fill_fragment(acc[i][j], 0.f);

    const int NK = F_DIM / 64;
    ISSUE2(0);
    for (int kc = 0; kc < NK; kc++) {
        if (kc + 1 < NK) { ISSUE2(kc + 1); cp_wait<1>(); }
        else             { cp_wait<0>(); }
        __syncthreads();
        const char* stg = dsm + (size_t)(kc & 1) * STAGE_B;
        const __nv_bfloat16* sAhi = (const __nv_bfloat16*)stg;
        const __nv_bfloat16* sAlo = (const __nv_bfloat16*)(stg + 18432);
        const __nv_bfloat16* sB   = (const __nv_bfloat16*)(stg + 36864);
        #pragma unroll
        for (int ks = 0; ks < 4; ks++) {
            wmma::fragment<wmma::matrix_b, 16, 16, 16, __nv_bfloat16, wmma::col_major> bf[4];
            #pragma unroll
            for (int nf = 0; nf < 4; nf++)
                wmma::load_matrix_sync(bf[nf], sB + (wn + nf * 16) * LDA + ks * 16, LDA);
            #pragma unroll
            for (int mf = 0; mf < 2; mf++) {
                wmma::fragment<wmma::matrix_a, 16, 16, 16, __nv_bfloat16, wmma::row_major> ah, al;
                wmma::load_matrix_sync(ah, sAhi + (wm + mf * 16) * LDA + ks * 16, LDA);
                wmma::load_matrix_sync(al, sAlo + (wm + mf * 16) * LDA + ks * 16, LDA);
                #pragma unroll
                for (int nf = 0; nf < 4; nf++) {
                    wmma::mma_sync(acc[mf][nf], ah, bf[nf], acc[mf][nf]);
                    wmma::mma_sync(acc[mf][nf], al, bf[nf], acc[mf][nf]);
                }
            }
        }
        __syncthreads();
    }
    #pragma unroll
    for (int mf = 0; mf < 2; mf++)
        #pragma unroll
        for (int nf = 0; nf < 4; nf++)
            wmma::store_matrix_sync(S + (wm + mf * 16) * LDS_ + wn + nf * 16,
                                    acc[mf][nf], LDS_, wmma::mem_row_major);
    __syncthreads();

    {
        const int row = tid >> 1, h0 = (tid & 1) * 64;
        if (m0 + row < cnt) {
            const size_t prow = (size_t)sSlot[row] * H_DIM + n0 + h0;
            #pragma unroll
            for (int q = 0; q < 16; q++) {
                float4 o = make_float4(S[row * LDS_ + h0 + q * 4],
                                       S[row * LDS_ + h0 + q * 4 + 1],
                                       S[row * LDS_ + h0 + q * 4 + 2],
                                       S[row * LDS_ + h0 + q * 4 + 3]);
                ((float4*)(g_part + prow))[q] = o;
            }
        }
    }
}

// deterministic 4-way reduce; dtype-flexible output
__global__ void k_reduce(void* __restrict__ outv) {
    int idx = blockIdx.x * 256 + threadIdx.x;
    int t = idx / (H_DIM / 4);
    int c = idx % (H_DIM / 4);
    const float4* p = (const float4*)g_part;
    float4 a = p[(size_t)(t * 4 + 0) * (H_DIM / 4) + c];
    float4 b = p[(size_t)(t * 4 + 1) * (H_DIM / 4) + c];
    float4 d = p[(size_t)(t * 4 + 2) * (H_DIM / 4) + c];
    float4 e = p[(size_t)(t * 4 + 3) * (H_DIM / 4) + c];
    float s0 = a.x + b.x + d.x + e.x, s1 = a.y + b.y + d.y + e.y;
    float s2 = a.z + b.z + d.z + e.z, s3 = a.w + b.w + d.w + e.w;
    if (g_bf[7]) {
        __nv_bfloat16* ob = (__nv_bfloat16*)outv;
        size_t base = (size_t)t * H_DIM + c * 4;
        ob[base + 0] = __float2bfloat16(s0);
        ob[base + 1] = __float2bfloat16(s1);
        ob[base + 2] = __float2bfloat16(s2);
        ob[base + 3] = __float2bfloat16(s3);
    } else {
        ((float4*)outv)[(size_t)t * (H_DIM / 4) + c] = make_float4(s0, s1, s2, s3);
    }
}

extern "C" void kernel_launch(void* const* d_in, const int* in_sizes, int n_in,
                              void* d_out, int out_size) {
    InPtrs in;
    int n = (n_in < 8) ? n_in : 8;
    for (int i = 0; i < 8; i++) {
        in.p[i]  = (i < n) ? d_in[i] : nullptr;
        in.sz[i] = (i < n) ? (long long)in_sizes[i] : 0;
    }
    in.n = n;

    const int DSMEM = 2 * STAGE_B;   // 110592 (covers 67584 epilogue buffer)
    cudaFuncSetAttribute(k_mma1, cudaFuncAttributeMaxDynamicSharedMemorySize, DSMEM);
    cudaFuncSetAttribute(k_mma2, cudaFuncAttributeMaxDynamicSharedMemorySize, DSMEM);

    k_resolve<<<1, 256>>>(in);
    k_deq_gu<<<(NEXP * 2 * F_DIM * (H_DIM / 2) / 4) / 256, 256>>>();
    k_deq_dn<<<(NEXP * H_DIM * (F_DIM / 2) / 4) / 256, 256>>>();
    k_split_x<<<(T_TOK * H_DIM / 4) / 256, 256>>>();
    k_route<<<NSLOT / 256, 256>>>();
    k_mma1<<<dim3(F_DIM / 64, NSLOT / 128, NEXP), 256, DSMEM>>>();
    k_mma2<<<dim3(H_DIM / 128, NSLOT / 128, NEXP), 256, DSMEM>>>();
    k_reduce<<<(T_TOK * H_DIM / 4) / 256, 256>>>(d_out);
}